// round 2
// baseline (speedup 1.0000x reference)
#include <cuda_runtime.h>
#include <math.h>

#define NB 4
#define DIMC 256
#define HH 64
#define WW 64
#define NPOS (HH*WW)
#define NHEAD 4
#define HD 64

// ---------------- scratch (device globals; no allocation allowed) ----------------
__device__ float g_qraw[NB*NPOS*DIMC];       // gemm1 out [b][n][o]
__device__ float g_qt[NB*NPOS*DIMC];         // LN(q)*scale [b][n][o]
__device__ float g_kctx[NB*49*DIMC];         // pooled ctx [b][l][c]
__device__ float g_kf[NB*49*DIMC];           // LN(k) [b][l][c]
__device__ float g_kfp[NB*NHEAD*HD*80];      // folded Wproj [bg][c][m<74, pad 80]
__device__ float g_attn[NB*NHEAD*NPOS*52];   // softmaxed attn [bg][n][tap, pad 52]
__device__ float g_mid[NB*NPOS*DIMC];        // AV out [b][n][c]

// ---------------- GEMM1: qraw[b][n][o] = sum_c x[b][c][n] * Wq[o][c] ----------------
__global__ __launch_bounds__(256) void gemm1_kernel(const float* __restrict__ x,
                                                    const float* __restrict__ Wq) {
    __shared__ float As[8][128];
    __shared__ float Bs[8][132];
    int b  = blockIdx.z;
    int n0 = blockIdx.x * 128;
    int o0 = blockIdx.y * 128;
    const float* xb = x + (size_t)b * DIMC * NPOS;
    int tid = threadIdx.x;
    int tx = tid & 15, ty = tid >> 4;
    float acc[8][8];
#pragma unroll
    for (int i = 0; i < 8; i++)
#pragma unroll
        for (int j = 0; j < 8; j++) acc[i][j] = 0.f;
    int ka = tid >> 5, na = (tid & 31) * 4;
    int ob = tid >> 1, kb = (tid & 1) * 4;
    for (int kc = 0; kc < DIMC; kc += 8) {
        float4 av = *reinterpret_cast<const float4*>(xb + (size_t)(kc + ka) * NPOS + n0 + na);
        float4 bv = *reinterpret_cast<const float4*>(Wq + (size_t)(o0 + ob) * DIMC + kc + kb);
        *reinterpret_cast<float4*>(&As[ka][na]) = av;
        Bs[kb+0][ob] = bv.x; Bs[kb+1][ob] = bv.y; Bs[kb+2][ob] = bv.z; Bs[kb+3][ob] = bv.w;
        __syncthreads();
#pragma unroll
        for (int k = 0; k < 8; k++) {
            float ar[8], br[8];
#pragma unroll
            for (int i = 0; i < 4; i++) { ar[i] = As[k][tx*4+i]; ar[4+i] = As[k][64+tx*4+i]; }
#pragma unroll
            for (int j = 0; j < 4; j++) { br[j] = Bs[k][ty*4+j]; br[4+j] = Bs[k][64+ty*4+j]; }
#pragma unroll
            for (int i = 0; i < 8; i++)
#pragma unroll
                for (int j = 0; j < 8; j++) acc[i][j] += ar[i]*br[j];
        }
        __syncthreads();
    }
    float* op = g_qraw + (size_t)b * NPOS * DIMC;
#pragma unroll
    for (int i = 0; i < 8; i++) {
        int n = n0 + (i < 4 ? tx*4 + i : 64 + tx*4 + (i-4));
#pragma unroll
        for (int jh = 0; jh < 2; jh++) {
            int o = o0 + jh*64 + ty*4;
            float4 v = make_float4(acc[i][jh*4], acc[i][jh*4+1], acc[i][jh*4+2], acc[i][jh*4+3]);
            *reinterpret_cast<float4*>(op + (size_t)n * DIMC + o) = v;
        }
    }
}

// ---------------- LN over 256 channels per (b,n), then *SCALE ----------------
__global__ __launch_bounds__(256) void ln_q_kernel(const float* __restrict__ gq,
                                                   const float* __restrict__ bq) {
    int row  = blockIdx.x * 8 + (threadIdx.x >> 5);
    int lane = threadIdx.x & 31;
    const float* rp = g_qraw + (size_t)row * DIMC;
    float v[8], s = 0.f, s2 = 0.f;
#pragma unroll
    for (int i = 0; i < 8; i++) { float t = rp[lane + 32*i]; v[i] = t; s += t; s2 += t*t; }
#pragma unroll
    for (int o = 16; o >= 1; o >>= 1) {
        s  += __shfl_xor_sync(0xffffffffu, s,  o);
        s2 += __shfl_xor_sync(0xffffffffu, s2, o);
    }
    float mu  = s  * (1.f/DIMC);
    float var = s2 * (1.f/DIMC) - mu*mu;
    float rs  = rsqrtf(var + 1e-6f);
    float* wp = g_qt + (size_t)row * DIMC;
#pragma unroll
    for (int i = 0; i < 8; i++) {
        int o = lane + 32*i;
        wp[o] = ((v[i]-mu)*rs*gq[o] + bq[o]) * 0.125f;   // SCALE = 64^-0.5
    }
}

// ---------------- ctx 8x8 avg pool: kctx[b][l][c] ----------------
__global__ void pool_kernel(const float* __restrict__ ctx) {
    int idx = blockIdx.x*256 + threadIdx.x;
    if (idx >= NB*49*DIMC) return;
    int c = idx & 255;
    int l = (idx >> 8) % 49;
    int b = idx / (49*256);
    int li = l / 7, lj = l % 7;
    const float* p = ctx + ((size_t)(b*DIMC + c)*56 + li*8)*56 + lj*8;
    float s = 0.f;
#pragma unroll
    for (int ii = 0; ii < 8; ii++)
#pragma unroll
        for (int jj = 0; jj < 8; jj++) s += p[ii*56 + jj];
    g_kctx[idx] = s * (1.f/64.f);
}

// ---------------- kf = LN(Wk @ kctx) per (b,l) row ----------------
__global__ __launch_bounds__(256) void kf_kernel(const float* __restrict__ Wk,
                                                 const float* __restrict__ gk,
                                                 const float* __restrict__ bk) {
    __shared__ float xs[DIMC];
    __shared__ float red[20];
    int bl = blockIdx.x;
    int o  = threadIdx.x;
    xs[o] = g_kctx[(size_t)bl*DIMC + o];
    __syncthreads();
    float acc = 0.f;
    const float* w = Wk + (size_t)o*DIMC;
    for (int c = 0; c < DIMC; c += 4) {
        float4 wv = *(const float4*)(w + c);
        acc += wv.x*xs[c] + wv.y*xs[c+1] + wv.z*xs[c+2] + wv.w*xs[c+3];
    }
    float s = acc, s2 = acc*acc;
#pragma unroll
    for (int m = 16; m >= 1; m >>= 1) {
        s  += __shfl_xor_sync(0xffffffffu, s,  m);
        s2 += __shfl_xor_sync(0xffffffffu, s2, m);
    }
    if ((o & 31) == 0) { red[o>>5] = s; red[8 + (o>>5)] = s2; }
    __syncthreads();
    if (o == 0) {
        float ts = 0.f, ts2 = 0.f;
        for (int i = 0; i < 8; i++) { ts += red[i]; ts2 += red[8+i]; }
        red[16] = ts; red[17] = ts2;
    }
    __syncthreads();
    float mu  = red[16]*(1.f/DIMC);
    float var = red[17]*(1.f/DIMC) - mu*mu;
    g_kf[(size_t)bl*DIMC + o] = (acc-mu)*rsqrtf(var+1e-6f)*gk[o] + bk[o];
}

// ---------------- fold Wproj: kfp[bg][c][m] = sum_l kf[b][l][g*64+c]*Wproj[m][l] ----------------
__global__ void kfp_kernel(const float* __restrict__ Wproj) {
    int idx = blockIdx.x*256 + threadIdx.x;
    if (idx >= NB*NHEAD*HD*80) return;
    int m  = idx % 80;
    int c  = (idx / 80) & 63;
    int bg = idx / (80*64);
    int b  = bg >> 2, gg = bg & 3;
    float s = 0.f;
    if (m < 74) {
        const float* wp = Wproj + m*49;
        for (int l = 0; l < 49; l++)
            s += g_kf[(size_t)(b*49 + l)*DIMC + gg*HD + c] * wp[l];
    }
    g_kfp[idx] = s;
}

// ---------------- wgt GEMM [64x80x64] + RPB + softmax, per (b,g,n-tile of 64) ----------------
__global__ __launch_bounds__(256) void wgt_softmax_kernel(const float* __restrict__ rpb1,
                                                          const float* __restrict__ rpb2) {
    __shared__ float As[64][68];
    __shared__ float Bs[64][80];
    int n0 = blockIdx.x * 64;
    int gy = blockIdx.y;            // b*4 + g
    int b  = gy >> 2, g = gy & 3;
    int tid = threadIdx.x;
    {   // load A: q_t[b][n0+r][g*64 + c]
        int r = tid >> 2, quad = tid & 3;
        const float* src = g_qt + ((size_t)(b*NPOS + n0 + r))*DIMC + g*HD + quad*16;
#pragma unroll
        for (int s = 0; s < 4; s++)
            *(float4*)(&As[r][quad*16 + s*4]) = *(const float4*)(src + s*4);
    }
    {   // load B: kfp slice, contiguous 64*80
        const float4* src = (const float4*)(g_kfp + (size_t)gy * HD * 80);
        float4* dst = (float4*)(&Bs[0][0]);
        for (int idx = tid; idx < HD*80/4; idx += 256) dst[idx] = src[idx];
    }
    __syncthreads();
    int tx = tid & 15, ty = tid >> 4;   // tx: 5 cols each (80), ty: 4 rows each (64)
    float acc[4][5];
#pragma unroll
    for (int r = 0; r < 4; r++)
#pragma unroll
        for (int j = 0; j < 5; j++) acc[r][j] = 0.f;
#pragma unroll
    for (int c = 0; c < 64; c++) {
        float ar[4], br[5];
#pragma unroll
        for (int r = 0; r < 4; r++) ar[r] = As[ty*4+r][c];
#pragma unroll
        for (int j = 0; j < 5; j++) br[j] = Bs[c][tx*5+j];
#pragma unroll
        for (int r = 0; r < 4; r++)
#pragma unroll
            for (int j = 0; j < 5; j++) acc[r][j] += ar[r]*br[j];
    }
    const float* rpb = (g < 2) ? (rpb1 + g*81) : (rpb2 + (g-2)*169);
#pragma unroll
    for (int r = 0; r < 4; r++) {
        int n = n0 + ty*4 + r;
        int i = n >> 6, j = n & 63;
        float vals[5];
        int   taps[5];
        bool  ok[5];
        if (g < 2) {
            int si = min(max(i-2,0),HH-5), sj = min(max(j-2,0),WW-5);
            int bi = 4 - (i - si), bj = 4 - (j - sj);
#pragma unroll
            for (int j5 = 0; j5 < 5; j5++) {
                int m = tx*5 + j5;
                bool v = (m < 25);
                int p = m/5, q = m - p*5;
                ok[j5] = v; taps[j5] = m;
                vals[j5] = v ? acc[r][j5] + rpb[(bi+p)*9 + bj + q] : -1e30f;
            }
        } else {
            int si = min(max(i-3,0),HH-7), sj = min(max(j-3,0),WW-7);
            int bi = 6 - (i - si), bj = 6 - (j - sj);
#pragma unroll
            for (int j5 = 0; j5 < 5; j5++) {
                int m = tx*5 + j5;
                int tap = m - 25;
                bool v = (m >= 25) && (m < 74);
                int p = tap/7, q = tap - p*7;
                ok[j5] = v; taps[j5] = tap;
                vals[j5] = v ? acc[r][j5] + rpb[(bi+p)*13 + bj + q] : -1e30f;
            }
        }
        float mx = vals[0];
#pragma unroll
        for (int j5 = 1; j5 < 5; j5++) mx = fmaxf(mx, vals[j5]);
#pragma unroll
        for (int o = 8; o >= 1; o >>= 1) mx = fmaxf(mx, __shfl_xor_sync(0xffffffffu, mx, o));
        float sum = 0.f;
#pragma unroll
        for (int j5 = 0; j5 < 5; j5++) {
            float e = ok[j5] ? __expf(vals[j5]-mx) : 0.f;
            vals[j5] = e; sum += e;
        }
#pragma unroll
        for (int o = 8; o >= 1; o >>= 1) sum += __shfl_xor_sync(0xffffffffu, sum, o);
        float inv = 1.f / sum;
        float* arow = g_attn + ((size_t)(gy*NPOS + n))*52;
#pragma unroll
        for (int j5 = 0; j5 < 5; j5++)
            if (ok[j5]) arow[taps[j5]] = vals[j5]*inv;
    }
}

// ---------------- neighborhood AV: mid[b][n][g*64+c] = sum_pq attn * x-window ----------------
template<int KK>
__global__ __launch_bounds__(256) void av_kernel(const float* __restrict__ x, int gbase) {
    const int HALO = 8 + KK - 1;
    extern __shared__ float vs[];   // [HALO*HALO][68]
    int ti0 = (blockIdx.x >> 3) * 8, tj0 = (blockIdx.x & 7) * 8;
    int g = gbase + blockIdx.y;
    int b = blockIdx.z;
    int hbi = min(max(ti0 - KK/2, 0), HH - HALO);
    int hbj = min(max(tj0 - KK/2, 0), WW - HALO);
    const float* xb = x + (size_t)(b*DIMC + g*HD)*NPOS;
    for (int idx = threadIdx.x; idx < HALO*HALO*HD; idx += 256) {
        int c  = idx / (HALO*HALO);
        int rr = idx - c*HALO*HALO;
        int ri = rr / HALO, rj = rr - ri*HALO;
        vs[rr*68 + c] = xb[(size_t)c*NPOS + (hbi+ri)*WW + hbj + rj];
    }
    __syncthreads();
    int t = threadIdx.x;
    int pos = t >> 2, cg = t & 3;
    int i = ti0 + (pos >> 3), j = tj0 + (pos & 7);
    int n = i*WW + j;
    int si = min(max(i - KK/2, 0), HH-KK) - hbi;
    int sj = min(max(j - KK/2, 0), WW-KK) - hbj;
    const float* arow = g_attn + ((size_t)((b*NHEAD+g)*NPOS + n))*52;
    float4 a0 = make_float4(0,0,0,0), a1 = a0, a2 = a0, a3 = a0;
#pragma unroll
    for (int p = 0; p < KK; p++) {
#pragma unroll
        for (int q = 0; q < KK; q++) {
            float a = __ldg(arow + p*KK + q);
            const float4* vp = reinterpret_cast<const float4*>(&vs[((si+p)*HALO + sj+q)*68 + cg*16]);
            float4 v0 = vp[0], v1 = vp[1], v2 = vp[2], v3 = vp[3];
            a0.x += a*v0.x; a0.y += a*v0.y; a0.z += a*v0.z; a0.w += a*v0.w;
            a1.x += a*v1.x; a1.y += a*v1.y; a1.z += a*v1.z; a1.w += a*v1.w;
            a2.x += a*v2.x; a2.y += a*v2.y; a2.z += a*v2.z; a2.w += a*v2.w;
            a3.x += a*v3.x; a3.y += a*v3.y; a3.z += a*v3.z; a3.w += a*v3.w;
        }
    }
    float* op = g_mid + ((size_t)(b*NPOS + n))*DIMC + g*HD + cg*16;
    ((float4*)op)[0] = a0; ((float4*)op)[1] = a1; ((float4*)op)[2] = a2; ((float4*)op)[3] = a3;
}

// ---------------- GEMM2 + BN: out[b][o][n] = bn(Wdy @ mid) ----------------
__global__ __launch_bounds__(256) void gemm2_kernel(const float* __restrict__ Wdy,
                                                    const float* __restrict__ bn_g,
                                                    const float* __restrict__ bn_b,
                                                    float* __restrict__ out) {
    __shared__ float As[8][132];
    __shared__ float Bs[8][132];
    int b  = blockIdx.z;
    int n0 = blockIdx.x * 128;
    int o0 = blockIdx.y * 128;
    const float* mb = g_mid + (size_t)b * NPOS * DIMC;
    int tid = threadIdx.x;
    int tx = tid & 15, ty = tid >> 4;
    float acc[8][8];
#pragma unroll
    for (int i = 0; i < 8; i++)
#pragma unroll
        for (int j = 0; j < 8; j++) acc[i][j] = 0.f;
    int na = tid >> 1, ka = (tid & 1) * 4;
    for (int kc = 0; kc < DIMC; kc += 8) {
        float4 av = *(const float4*)(mb  + (size_t)(n0 + na) * DIMC + kc + ka);
        float4 bv = *(const float4*)(Wdy + (size_t)(o0 + na) * DIMC + kc + ka);
        As[ka+0][na] = av.x; As[ka+1][na] = av.y; As[ka+2][na] = av.z; As[ka+3][na] = av.w;
        Bs[ka+0][na] = bv.x; Bs[ka+1][na] = bv.y; Bs[ka+2][na] = bv.z; Bs[ka+3][na] = bv.w;
        __syncthreads();
#pragma unroll
        for (int k = 0; k < 8; k++) {
            float ar[8], br[8];
#pragma unroll
            for (int i = 0; i < 4; i++) { ar[i] = As[k][tx*4+i]; ar[4+i] = As[k][64+tx*4+i]; }
#pragma unroll
            for (int j = 0; j < 4; j++) { br[j] = Bs[k][ty*4+j]; br[4+j] = Bs[k][64+ty*4+j]; }
#pragma unroll
            for (int i = 0; i < 8; i++)
#pragma unroll
                for (int j = 0; j < 8; j++) acc[i][j] += ar[i]*br[j];
        }
        __syncthreads();
    }
#pragma unroll
    for (int j = 0; j < 8; j++) {
        int o = o0 + (j < 4 ? ty*4 + j : 64 + ty*4 + (j-4));
        float sc = bn_g[o] * rsqrtf(1.f + 1e-5f);
        float sh = bn_b[o];
        float4 v1 = make_float4(acc[0][j]*sc+sh, acc[1][j]*sc+sh, acc[2][j]*sc+sh, acc[3][j]*sc+sh);
        float4 v2 = make_float4(acc[4][j]*sc+sh, acc[5][j]*sc+sh, acc[6][j]*sc+sh, acc[7][j]*sc+sh);
        float* op = out + ((size_t)(b*DIMC + o)) * NPOS;
        *reinterpret_cast<float4*>(op + n0 + tx*4)      = v1;
        *reinterpret_cast<float4*>(op + n0 + 64 + tx*4) = v2;
    }
}

extern "C" void kernel_launch(void* const* d_in, const int* in_sizes, int n_in,
                              void* d_out, int out_size) {
    const float* x     = (const float*)d_in[0];
    const float* ctx   = (const float*)d_in[1];
    const float* Wq    = (const float*)d_in[2];
    const float* gq    = (const float*)d_in[3];
    const float* bq    = (const float*)d_in[4];
    const float* Wk    = (const float*)d_in[5];
    const float* gk    = (const float*)d_in[6];
    const float* bk    = (const float*)d_in[7];
    const float* Wproj = (const float*)d_in[8];
    const float* rpb1  = (const float*)d_in[9];
    const float* rpb2  = (const float*)d_in[10];
    const float* Wdy   = (const float*)d_in[11];
    const float* bn_g  = (const float*)d_in[12];
    const float* bn_b  = (const float*)d_in[13];
    float* out = (float*)d_out;

    cudaFuncSetAttribute(av_kernel<7>, cudaFuncAttributeMaxDynamicSharedMemorySize, 14*14*68*4);

    gemm1_kernel<<<dim3(32, 2, NB), 256>>>(x, Wq);
    ln_q_kernel<<<NB*NPOS/8, 256>>>(gq, bq);
    pool_kernel<<<(NB*49*DIMC + 255)/256, 256>>>(ctx);
    kf_kernel<<<NB*49, 256>>>(Wk, gk, bk);
    kfp_kernel<<<(NB*NHEAD*HD*80 + 255)/256, 256>>>(Wproj);
    wgt_softmax_kernel<<<dim3(64, 16), 256>>>(rpb1, rpb2);
    av_kernel<5><<<dim3(64, 2, NB), 256, 12*12*68*4>>>(x, 0);
    av_kernel<7><<<dim3(64, 2, NB), 256, 14*14*68*4>>>(x, 2);
    gemm2_kernel<<<dim3(32, 2, NB), 256>>>(Wdy, bn_g, bn_b, out);
}

// round 4
// speedup vs baseline: 1.4020x; 1.4020x over previous
#include <cuda_runtime.h>
#include <cstdint>
#include <math.h>

#define NB 4
#define DIMC 256
#define HH 64
#define WW 64
#define NPOS (HH*WW)
#define NHEAD 4
#define HD 64

// ---------------- scratch ----------------
__device__ float g_xt[NB*NPOS*DIMC];         // x transposed [b][n][c]
__device__ float g_qraw[NB*NPOS*DIMC];       // gemm1 raw [b][n][o]
__device__ float g_qt[NB*NPOS*DIMC];         // LN(q)*scale [b][n][o]
__device__ float g_kctx[NB*49*DIMC];         // pooled ctx [row=(b*49+l)][c]
__device__ float g_kraw[256*DIMC];           // Wk@kctx raw (196 rows used)
__device__ float g_kf[NB*49*DIMC];           // LN(k)
__device__ float g_kfp[NB*NHEAD*HD*80];      // folded Wproj [bg][c][m<74, pad 80]
__device__ float g_attn[NB*NHEAD*NPOS*52];   // softmaxed attn
__device__ float g_mid[NB*NPOS*DIMC];        // AV out [b][n][c]

__device__ __forceinline__ uint32_t f2tf32(float f) {
    uint32_t r; asm("cvt.rna.tf32.f32 %0, %1;" : "=r"(r) : "f"(f)); return r;
}

// ================= transpose: x[b][c][n] -> xt[b][n][c] =================
__global__ __launch_bounds__(256) void transpose_kernel(const float* __restrict__ x) {
    __shared__ float tile[32][33];
    int n0 = blockIdx.x * 32, c0 = blockIdx.y * 32, b = blockIdx.z;
    int tx = threadIdx.x, ty = threadIdx.y;
    const float* xb = x + (size_t)b * DIMC * NPOS;
#pragma unroll
    for (int k = 0; k < 4; k++) {
        int cl = ty + k * 8;
        tile[cl][tx] = xb[(size_t)(c0 + cl) * NPOS + n0 + tx];
    }
    __syncthreads();
    float* xtb = g_xt + (size_t)b * NPOS * DIMC;
#pragma unroll
    for (int k = 0; k < 4; k++) {
        int nl = ty + k * 8;
        xtb[(size_t)(n0 + nl) * DIMC + c0 + tx] = tile[tx][nl];
    }
}

// ================= mma.sync tf32 GEMM =================
// D[m=row n][o] = sum_c A[row][c] * B[o][c]   (A: [M x 256] k-major, B: [256 x 256] k-major)
// EPI 0: raw store  Out[row*256 + o]   (row < mvalid)
// EPI 1: BN + transposed store Out[(z*256 + o)*NPOS + row]
template<int EPI>
__global__ __launch_bounds__(256, 2)
void mma_gemm_kernel(const float* __restrict__ A, const float* __restrict__ B,
                     float* __restrict__ Out, const float* __restrict__ p1,
                     const float* __restrict__ p2, int mvalid, int batchStride) {
    extern __shared__ uint32_t sm[];        // As[128*36] ++ Bs[128*36]
    uint32_t* As = sm;
    uint32_t* Bs = sm + 128 * 36;
    __shared__ float sp1[256], sp2[256];

    int tid = threadIdx.x;
    int wid = tid >> 5;
    int lane = tid & 31;
    int q = lane >> 2, tq = lane & 3;       // quad row / thread-in-quad
    int wm = wid >> 2, wn = wid & 3;        // warp grid 2(m) x 4(n)
    int z = blockIdx.z;
    int m0 = blockIdx.x * 128;
    int n0 = blockIdx.y * 128;
    const float* Ab = A + (size_t)z * batchStride;

    if (EPI == 1) { sp1[tid] = p1[tid] * rsqrtf(1.f + 1e-5f); sp2[tid] = p2[tid]; }

    float c[4][4][4];
#pragma unroll
    for (int mt = 0; mt < 4; mt++)
#pragma unroll
        for (int nt = 0; nt < 4; nt++)
#pragma unroll
            for (int i = 0; i < 4; i++) c[mt][nt][i] = 0.f;

    for (int ck = 0; ck < 8; ck++) {
        __syncthreads();
        // load A chunk [128 x 32] and B chunk [128 x 32]
#pragma unroll
        for (int t = 0; t < 4; t++) {
            int idx = tid + t * 256;
            int row = idx >> 3, c4 = idx & 7;
            int ga = min(m0 + row, mvalid - 1);
            float4 va = *(const float4*)(Ab + (size_t)ga * DIMC + ck * 32 + c4 * 4);
            float4 vb = *(const float4*)(B + (size_t)(n0 + row) * DIMC + ck * 32 + c4 * 4);
            uint32_t* ap = As + row * 36 + c4 * 4;
            ap[0] = f2tf32(va.x); ap[1] = f2tf32(va.y); ap[2] = f2tf32(va.z); ap[3] = f2tf32(va.w);
            uint32_t* bp = Bs + row * 36 + c4 * 4;
            bp[0] = f2tf32(vb.x); bp[1] = f2tf32(vb.y); bp[2] = f2tf32(vb.z); bp[3] = f2tf32(vb.w);
        }
        __syncthreads();
#pragma unroll
        for (int ks = 0; ks < 4; ks++) {
            int k0 = ks * 8;
            uint32_t a[4][4];
#pragma unroll
            for (int mt = 0; mt < 4; mt++) {
                int r = wm * 64 + mt * 16 + q;
                a[mt][0] = As[r * 36 + k0 + tq];
                a[mt][1] = As[(r + 8) * 36 + k0 + tq];
                a[mt][2] = As[r * 36 + k0 + tq + 4];
                a[mt][3] = As[(r + 8) * 36 + k0 + tq + 4];
            }
            uint32_t b[4][2];
#pragma unroll
            for (int nt = 0; nt < 4; nt++) {
                int nn = wn * 32 + nt * 8 + q;
                b[nt][0] = Bs[nn * 36 + k0 + tq];
                b[nt][1] = Bs[nn * 36 + k0 + tq + 4];
            }
#pragma unroll
            for (int mt = 0; mt < 4; mt++)
#pragma unroll
                for (int nt = 0; nt < 4; nt++) {
                    asm volatile(
                        "mma.sync.aligned.m16n8k8.row.col.f32.tf32.tf32.f32 "
                        "{%0,%1,%2,%3}, {%4,%5,%6,%7}, {%8,%9}, {%0,%1,%2,%3};"
                        : "+f"(c[mt][nt][0]), "+f"(c[mt][nt][1]),
                          "+f"(c[mt][nt][2]), "+f"(c[mt][nt][3])
                        : "r"(a[mt][0]), "r"(a[mt][1]), "r"(a[mt][2]), "r"(a[mt][3]),
                          "r"(b[nt][0]), "r"(b[nt][1]));
                }
        }
    }

    // epilogue
#pragma unroll
    for (int mt = 0; mt < 4; mt++) {
        int r0 = m0 + wm * 64 + mt * 16 + q;     // global row (n)
#pragma unroll
        for (int nt = 0; nt < 4; nt++) {
            int o0 = n0 + wn * 32 + nt * 8 + 2 * tq;  // global col (o)
            if (EPI == 0) {
                if (r0 < mvalid) {
                    float2 v = make_float2(c[mt][nt][0], c[mt][nt][1]);
                    *(float2*)(Out + (size_t)(z * NPOS + r0) * DIMC + o0) = v;
                }
                if (r0 + 8 < mvalid) {
                    float2 v = make_float2(c[mt][nt][2], c[mt][nt][3]);
                    *(float2*)(Out + (size_t)(z * NPOS + r0 + 8) * DIMC + o0) = v;
                }
            } else {
                float s0 = sp1[o0],     h0 = sp2[o0];
                float s1 = sp1[o0 + 1], h1 = sp2[o0 + 1];
                float* base0 = Out + ((size_t)(z * DIMC + o0)) * NPOS;
                float* base1 = Out + ((size_t)(z * DIMC + o0 + 1)) * NPOS;
                base0[r0]     = c[mt][nt][0] * s0 + h0;
                base1[r0]     = c[mt][nt][1] * s1 + h1;
                base0[r0 + 8] = c[mt][nt][2] * s0 + h0;
                base1[r0 + 8] = c[mt][nt][3] * s1 + h1;
            }
        }
    }
}

// ---------------- LN over 256 channels per row, *SCALE ----------------
__global__ __launch_bounds__(256) void ln_q_kernel(const float* __restrict__ gq,
                                                   const float* __restrict__ bq) {
    int row  = blockIdx.x * 8 + (threadIdx.x >> 5);
    int lane = threadIdx.x & 31;
    const float* rp = g_qraw + (size_t)row * DIMC;
    float v[8], s = 0.f, s2 = 0.f;
#pragma unroll
    for (int i = 0; i < 8; i++) { float t = rp[lane + 32*i]; v[i] = t; s += t; s2 += t*t; }
#pragma unroll
    for (int o = 16; o >= 1; o >>= 1) {
        s  += __shfl_xor_sync(0xffffffffu, s,  o);
        s2 += __shfl_xor_sync(0xffffffffu, s2, o);
    }
    float mu  = s  * (1.f/DIMC);
    float var = s2 * (1.f/DIMC) - mu*mu;
    float rs  = rsqrtf(var + 1e-6f);
    float* wp = g_qt + (size_t)row * DIMC;
#pragma unroll
    for (int i = 0; i < 8; i++) {
        int o = lane + 32*i;
        wp[o] = ((v[i]-mu)*rs*gq[o] + bq[o]) * 0.125f;
    }
}

// ---------------- LN for kf rows (196) ----------------
__global__ __launch_bounds__(256) void ln_k_kernel(const float* __restrict__ gk,
                                                   const float* __restrict__ bk) {
    int row = blockIdx.x * 8 + (threadIdx.x >> 5);
    if (row >= NB * 49) return;
    int lane = threadIdx.x & 31;
    const float* rp = g_kraw + (size_t)row * DIMC;
    float v[8], s = 0.f, s2 = 0.f;
#pragma unroll
    for (int i = 0; i < 8; i++) { float t = rp[lane + 32*i]; v[i] = t; s += t; s2 += t*t; }
#pragma unroll
    for (int o = 16; o >= 1; o >>= 1) {
        s  += __shfl_xor_sync(0xffffffffu, s,  o);
        s2 += __shfl_xor_sync(0xffffffffu, s2, o);
    }
    float mu = s * (1.f/DIMC);
    float var = s2 * (1.f/DIMC) - mu*mu;
    float rs = rsqrtf(var + 1e-6f);
    float* wp = g_kf + (size_t)row * DIMC;
#pragma unroll
    for (int i = 0; i < 8; i++) {
        int o = lane + 32*i;
        wp[o] = (v[i]-mu)*rs*gk[o] + bk[o];
    }
}

// ---------------- ctx 8x8 avg pool ----------------
__global__ void pool_kernel(const float* __restrict__ ctx) {
    int idx = blockIdx.x*256 + threadIdx.x;
    if (idx >= NB*49*DIMC) return;
    int c = idx & 255;
    int l = (idx >> 8) % 49;
    int b = idx / (49*256);
    int li = l / 7, lj = l % 7;
    const float* p = ctx + ((size_t)(b*DIMC + c)*56 + li*8)*56 + lj*8;
    float s = 0.f;
#pragma unroll
    for (int ii = 0; ii < 8; ii++)
#pragma unroll
        for (int jj = 0; jj < 8; jj++) s += p[ii*56 + jj];
    g_kctx[idx] = s * (1.f/64.f);
}

// ---------------- fold Wproj ----------------
__global__ void kfp_kernel(const float* __restrict__ Wproj) {
    int idx = blockIdx.x*256 + threadIdx.x;
    if (idx >= NB*NHEAD*HD*80) return;
    int m  = idx % 80;
    int c  = (idx / 80) & 63;
    int bg = idx / (80*64);
    int b  = bg >> 2, gg = bg & 3;
    float s = 0.f;
    if (m < 74) {
        const float* wp = Wproj + m*49;
        for (int l = 0; l < 49; l++)
            s += g_kf[(size_t)(b*49 + l)*DIMC + gg*HD + c] * wp[l];
    }
    g_kfp[idx] = s;
}

// ---------------- wgt GEMM + RPB + softmax ----------------
__global__ __launch_bounds__(256) void wgt_softmax_kernel(const float* __restrict__ rpb1,
                                                          const float* __restrict__ rpb2) {
    __shared__ float As[64][68];
    __shared__ float Bs[64][80];
    int n0 = blockIdx.x * 64;
    int gy = blockIdx.y;
    int b  = gy >> 2, g = gy & 3;
    int tid = threadIdx.x;
    {
        int r = tid >> 2, quad = tid & 3;
        const float* src = g_qt + ((size_t)(b*NPOS + n0 + r))*DIMC + g*HD + quad*16;
#pragma unroll
        for (int s = 0; s < 4; s++)
            *(float4*)(&As[r][quad*16 + s*4]) = *(const float4*)(src + s*4);
    }
    {
        const float4* src = (const float4*)(g_kfp + (size_t)gy * HD * 80);
        float4* dst = (float4*)(&Bs[0][0]);
        for (int idx = tid; idx < HD*80/4; idx += 256) dst[idx] = src[idx];
    }
    __syncthreads();
    int tx = tid & 15, ty = tid >> 4;
    float acc[4][5];
#pragma unroll
    for (int r = 0; r < 4; r++)
#pragma unroll
        for (int j = 0; j < 5; j++) acc[r][j] = 0.f;
#pragma unroll
    for (int c = 0; c < 64; c++) {
        float ar[4], br[5];
#pragma unroll
        for (int r = 0; r < 4; r++) ar[r] = As[ty*4+r][c];
#pragma unroll
        for (int j = 0; j < 5; j++) br[j] = Bs[c][tx*5+j];
#pragma unroll
        for (int r = 0; r < 4; r++)
#pragma unroll
            for (int j = 0; j < 5; j++) acc[r][j] += ar[r]*br[j];
    }
    const float* rpb = (g < 2) ? (rpb1 + g*81) : (rpb2 + (g-2)*169);
#pragma unroll
    for (int r = 0; r < 4; r++) {
        int n = n0 + ty*4 + r;
        int i = n >> 6, j = n & 63;
        float vals[5];
        int   taps[5];
        bool  ok[5];
        if (g < 2) {
            int si = min(max(i-2,0),HH-5), sj = min(max(j-2,0),WW-5);
            int bi = 4 - (i - si), bj = 4 - (j - sj);
#pragma unroll
            for (int j5 = 0; j5 < 5; j5++) {
                int m = tx*5 + j5;
                bool v = (m < 25);
                int p = m/5, qq = m - p*5;
                ok[j5] = v; taps[j5] = m;
                vals[j5] = v ? acc[r][j5] + rpb[(bi+p)*9 + bj + qq] : -1e30f;
            }
        } else {
            int si = min(max(i-3,0),HH-7), sj = min(max(j-3,0),WW-7);
            int bi = 6 - (i - si), bj = 6 - (j - sj);
#pragma unroll
            for (int j5 = 0; j5 < 5; j5++) {
                int m = tx*5 + j5;
                int tap = m - 25;
                bool v = (m >= 25) && (m < 74);
                int p = tap/7, qq = tap - p*7;
                ok[j5] = v; taps[j5] = tap;
                vals[j5] = v ? acc[r][j5] + rpb[(bi+p)*13 + bj + qq] : -1e30f;
            }
        }
        float mx = vals[0];
#pragma unroll
        for (int j5 = 1; j5 < 5; j5++) mx = fmaxf(mx, vals[j5]);
#pragma unroll
        for (int o = 8; o >= 1; o >>= 1) mx = fmaxf(mx, __shfl_xor_sync(0xffffffffu, mx, o));
        float sum = 0.f;
#pragma unroll
        for (int j5 = 0; j5 < 5; j5++) {
            float e = ok[j5] ? __expf(vals[j5]-mx) : 0.f;
            vals[j5] = e; sum += e;
        }
#pragma unroll
        for (int o = 8; o >= 1; o >>= 1) sum += __shfl_xor_sync(0xffffffffu, sum, o);
        float inv = 1.f / sum;
        float* arow = g_attn + ((size_t)(gy*NPOS + n))*52;
#pragma unroll
        for (int j5 = 0; j5 < 5; j5++)
            if (ok[j5]) arow[taps[j5]] = vals[j5]*inv;
    }
}

// ---------------- neighborhood AV ----------------
template<int KK>
__global__ __launch_bounds__(256) void av_kernel(const float* __restrict__ x, int gbase) {
    const int HALO = 8 + KK - 1;
    extern __shared__ float vs[];
    int ti0 = (blockIdx.x >> 3) * 8, tj0 = (blockIdx.x & 7) * 8;
    int g = gbase + blockIdx.y;
    int b = blockIdx.z;
    int hbi = min(max(ti0 - KK/2, 0), HH - HALO);
    int hbj = min(max(tj0 - KK/2, 0), WW - HALO);
    const float* xb = x + (size_t)(b*DIMC + g*HD)*NPOS;
    for (int idx = threadIdx.x; idx < HALO*HALO*HD; idx += 256) {
        int c  = idx / (HALO*HALO);
        int rr = idx - c*HALO*HALO;
        int ri = rr / HALO, rj = rr - ri*HALO;
        vs[rr*68 + c] = xb[(size_t)c*NPOS + (hbi+ri)*WW + hbj + rj];
    }
    __syncthreads();
    int t = threadIdx.x;
    int pos = t >> 2, cg = t & 3;
    int i = ti0 + (pos >> 3), j = tj0 + (pos & 7);
    int n = i*WW + j;
    int si = min(max(i - KK/2, 0), HH-KK) - hbi;
    int sj = min(max(j - KK/2, 0), WW-KK) - hbj;
    const float* arow = g_attn + ((size_t)((b*NHEAD+g)*NPOS + n))*52;
    float4 a0 = make_float4(0,0,0,0), a1 = a0, a2 = a0, a3 = a0;
#pragma unroll
    for (int p = 0; p < KK; p++) {
#pragma unroll
        for (int qq = 0; qq < KK; qq++) {
            float a = __ldg(arow + p*KK + qq);
            const float4* vp = reinterpret_cast<const float4*>(&vs[((si+p)*HALO + sj+qq)*68 + cg*16]);
            float4 v0 = vp[0], v1 = vp[1], v2 = vp[2], v3 = vp[3];
            a0.x += a*v0.x; a0.y += a*v0.y; a0.z += a*v0.z; a0.w += a*v0.w;
            a1.x += a*v1.x; a1.y += a*v1.y; a1.z += a*v1.z; a1.w += a*v1.w;
            a2.x += a*v2.x; a2.y += a*v2.y; a2.z += a*v2.z; a2.w += a*v2.w;
            a3.x += a*v3.x; a3.y += a*v3.y; a3.z += a*v3.z; a3.w += a*v3.w;
        }
    }
    float* op = g_mid + ((size_t)(b*NPOS + n))*DIMC + g*HD + cg*16;
    ((float4*)op)[0] = a0; ((float4*)op)[1] = a1; ((float4*)op)[2] = a2; ((float4*)op)[3] = a3;
}

extern "C" void kernel_launch(void* const* d_in, const int* in_sizes, int n_in,
                              void* d_out, int out_size) {
    const float* x     = (const float*)d_in[0];
    const float* ctx   = (const float*)d_in[1];
    const float* Wq    = (const float*)d_in[2];
    const float* gq    = (const float*)d_in[3];
    const float* bq    = (const float*)d_in[4];
    const float* Wk    = (const float*)d_in[5];
    const float* gk    = (const float*)d_in[6];
    const float* bk    = (const float*)d_in[7];
    const float* Wproj = (const float*)d_in[8];
    const float* rpb1  = (const float*)d_in[9];
    const float* rpb2  = (const float*)d_in[10];
    const float* Wdy   = (const float*)d_in[11];
    const float* bn_g  = (const float*)d_in[12];
    const float* bn_b  = (const float*)d_in[13];
    float* out = (float*)d_out;

    const int GSMEM = 2 * 128 * 36 * 4;   // 36864 bytes
    cudaFuncSetAttribute(av_kernel<7>, cudaFuncAttributeMaxDynamicSharedMemorySize, 14*14*68*4);
    cudaFuncSetAttribute(mma_gemm_kernel<0>, cudaFuncAttributeMaxDynamicSharedMemorySize, GSMEM);
    cudaFuncSetAttribute(mma_gemm_kernel<1>, cudaFuncAttributeMaxDynamicSharedMemorySize, GSMEM);

    static float *p_xt = nullptr, *p_kctx = nullptr, *p_kraw = nullptr, *p_mid = nullptr, *p_qraw = nullptr;
    if (!p_xt) {
        cudaGetSymbolAddress((void**)&p_xt,   g_xt);
        cudaGetSymbolAddress((void**)&p_kctx, g_kctx);
        cudaGetSymbolAddress((void**)&p_kraw, g_kraw);
        cudaGetSymbolAddress((void**)&p_mid,  g_mid);
        cudaGetSymbolAddress((void**)&p_qraw, g_qraw);
    }

    transpose_kernel<<<dim3(128, 8, NB), dim3(32, 8)>>>(x);
    pool_kernel<<<(NB*49*DIMC + 255)/256, 256>>>(ctx);
    // gemm1: qraw = xt @ Wq^T
    mma_gemm_kernel<0><<<dim3(32, 2, NB), 256, GSMEM>>>(p_xt, Wq, p_qraw, nullptr, nullptr, NPOS, NPOS*DIMC);
    ln_q_kernel<<<NB*NPOS/8, 256>>>(gq, bq);
    // kf: kraw = kctx @ Wk^T  (196 valid rows)
    mma_gemm_kernel<0><<<dim3(2, 2, 1), 256, GSMEM>>>(p_kctx, Wk, p_kraw, nullptr, nullptr, NB*49, 0);
    ln_k_kernel<<<25, 256>>>(gk, bk);
    kfp_kernel<<<(NB*NHEAD*HD*80 + 255)/256, 256>>>(Wproj);
    wgt_softmax_kernel<<<dim3(64, 16), 256>>>(rpb1, rpb2);
    av_kernel<5><<<dim3(64, 2, NB), 256, 12*12*68*4>>>(x, 0);
    av_kernel<7><<<dim3(64, 2, NB), 256, 14*14*68*4>>>(x, 2);
    // gemm2: out = BN(mid @ Wdy^T), stored transposed
    mma_gemm_kernel<1><<<dim3(32, 2, NB), 256, GSMEM>>>(p_mid, Wdy, out, bn_g, bn_b, NPOS, NPOS*DIMC);
}

// round 5
// speedup vs baseline: 1.4881x; 1.0614x over previous
#include <cuda_runtime.h>
#include <cstdint>
#include <math.h>

#define NB 4
#define DIMC 256
#define HH 64
#define WW 64
#define NPOS (HH*WW)
#define NHEAD 4
#define HD 64

// ---------------- scratch ----------------
__device__ float g_qt[NB*NPOS*DIMC];         // LN(q)*scale [b][n][o]
__device__ float g_kctx[NB*49*DIMC];         // pooled ctx [row=(b*49+l)][c]
__device__ float g_kraw[256*DIMC];           // Wk@kctx raw (196 rows used)
__device__ float g_kf[NB*49*DIMC];           // LN(k)
__device__ float g_kfp[NB*NHEAD*HD*80];      // folded Wproj [bg][c][m<74, pad 80]
__device__ float g_attn[NB*NHEAD*NPOS*52];   // softmaxed attn
__device__ float g_mid[NB*NPOS*DIMC];        // AV out [b][n][c]

__device__ __forceinline__ uint32_t f2tf32(float f) {
    uint32_t r; asm("cvt.rna.tf32.f32 %0, %1;" : "=r"(r) : "f"(f)); return r;
}

// ================= gemm1 + fused LN =================
// qt[b][n][o] = LN_o( sum_c x[b][c][n] * Wq[o][c] ) * gq * 0.125 + bq*0.125
// Block: 128 rows(n) x 256 cols(o), 512 threads (16 warps, 2 m x 8 n)
#define ASTR 136
__global__ __launch_bounds__(512, 1)
void gemm1_ln_kernel(const float* __restrict__ x, const float* __restrict__ Wq,
                     const float* __restrict__ gq, const float* __restrict__ bq) {
    extern __shared__ uint32_t sm[];                 // As2[32*ASTR] ++ Bs[256*36]
    uint32_t* As2 = sm;
    uint32_t* Bs  = sm + 32 * ASTR;
    __shared__ float red_s[128][9];
    __shared__ float red_s2[128][9];
    __shared__ float sg[256], sb[256];

    int tid  = threadIdx.x;
    int wid  = tid >> 5, lane = tid & 31;
    int q    = lane >> 2, tq = lane & 3;
    int wm   = wid >> 3, wn = wid & 7;               // 2 x 8
    int z    = blockIdx.z;
    int m0   = blockIdx.x * 128;
    const float* xb = x + (size_t)z * DIMC * NPOS;

    if (tid < 256) { sg[tid] = gq[tid]; sb[tid] = bq[tid]; }

    float c[4][4][4];
#pragma unroll
    for (int mt = 0; mt < 4; mt++)
#pragma unroll
        for (int nt = 0; nt < 4; nt++)
#pragma unroll
            for (int i = 0; i < 4; i++) c[mt][nt][i] = 0.f;

    for (int ck = 0; ck < 8; ck++) {
        __syncthreads();
        // A chunk: x[c = ck*32 + cc][n = m0..m0+127] -> As2[cc*ASTR + n]  (transposed store)
#pragma unroll
        for (int it = 0; it < 2; it++) {
            int slot = tid + it * 512;               // 1024 float4 slots
            int cc = slot >> 5, n4 = slot & 31;
            float4 v = *(const float4*)(xb + (size_t)(ck * 32 + cc) * NPOS + m0 + n4 * 4);
            uint4 u = make_uint4(f2tf32(v.x), f2tf32(v.y), f2tf32(v.z), f2tf32(v.w));
            *(uint4*)(As2 + cc * ASTR + n4 * 4) = u;
        }
        // B chunk: Wq[o][ck*32 + ..] -> Bs[o*36 + ..]
#pragma unroll
        for (int it = 0; it < 4; it++) {
            int slot = tid + it * 512;               // 2048 float4 slots
            int row = slot >> 3, c4 = slot & 7;
            float4 v = *(const float4*)(Wq + (size_t)row * DIMC + ck * 32 + c4 * 4);
            uint4 u = make_uint4(f2tf32(v.x), f2tf32(v.y), f2tf32(v.z), f2tf32(v.w));
            *(uint4*)(Bs + row * 36 + c4 * 4) = u;
        }
        __syncthreads();
#pragma unroll
        for (int ks = 0; ks < 4; ks++) {
            int k0 = ks * 8;
            uint32_t a[4][4];
#pragma unroll
            for (int mt = 0; mt < 4; mt++) {
                int r = wm * 64 + mt * 16 + q;
                a[mt][0] = As2[(k0 + tq) * ASTR + r];
                a[mt][1] = As2[(k0 + tq) * ASTR + r + 8];
                a[mt][2] = As2[(k0 + tq + 4) * ASTR + r];
                a[mt][3] = As2[(k0 + tq + 4) * ASTR + r + 8];
            }
            uint32_t b[4][2];
#pragma unroll
            for (int nt = 0; nt < 4; nt++) {
                int o = wn * 32 + nt * 8 + q;
                b[nt][0] = Bs[o * 36 + k0 + tq];
                b[nt][1] = Bs[o * 36 + k0 + tq + 4];
            }
#pragma unroll
            for (int mt = 0; mt < 4; mt++)
#pragma unroll
                for (int nt = 0; nt < 4; nt++) {
                    asm volatile(
                        "mma.sync.aligned.m16n8k8.row.col.f32.tf32.tf32.f32 "
                        "{%0,%1,%2,%3}, {%4,%5,%6,%7}, {%8,%9}, {%0,%1,%2,%3};"
                        : "+f"(c[mt][nt][0]), "+f"(c[mt][nt][1]),
                          "+f"(c[mt][nt][2]), "+f"(c[mt][nt][3])
                        : "r"(a[mt][0]), "r"(a[mt][1]), "r"(a[mt][2]), "r"(a[mt][3]),
                          "r"(b[nt][0]), "r"(b[nt][1]));
                }
        }
    }

    // ---- fused LN epilogue ----
    // per-row partials over this thread's 8 cols, per (mt, half)
#pragma unroll
    for (int mt = 0; mt < 4; mt++) {
#pragma unroll
        for (int h = 0; h < 2; h++) {
            float s = 0.f, s2 = 0.f;
#pragma unroll
            for (int nt = 0; nt < 4; nt++) {
                float v0 = c[mt][nt][2*h], v1 = c[mt][nt][2*h+1];
                s += v0 + v1; s2 += v0*v0 + v1*v1;
            }
            s  += __shfl_xor_sync(0xffffffffu, s, 1);
            s2 += __shfl_xor_sync(0xffffffffu, s2, 1);
            s  += __shfl_xor_sync(0xffffffffu, s, 2);
            s2 += __shfl_xor_sync(0xffffffffu, s2, 2);
            if (tq == 0) {
                int rl = wm * 64 + mt * 16 + q + h * 8;
                red_s[rl][wn] = s;
                red_s2[rl][wn] = s2;
            }
        }
    }
    __syncthreads();
    float* outb = g_qt + (size_t)z * NPOS * DIMC;
#pragma unroll
    for (int mt = 0; mt < 4; mt++) {
#pragma unroll
        for (int h = 0; h < 2; h++) {
            int rl = wm * 64 + mt * 16 + q + h * 8;
            float S = 0.f, S2 = 0.f;
#pragma unroll
            for (int w = 0; w < 8; w++) { S += red_s[rl][w]; S2 += red_s2[rl][w]; }
            float mu = S * (1.f/256.f);
            float var = S2 * (1.f/256.f) - mu * mu;
            float rs = rsqrtf(var + 1e-6f);
            float* rowp = outb + (size_t)(m0 + rl) * DIMC;
#pragma unroll
            for (int nt = 0; nt < 4; nt++) {
                int o = wn * 32 + nt * 8 + 2 * tq;
                float2 v;
                v.x = ((c[mt][nt][2*h]   - mu) * rs * sg[o]   + sb[o])   * 0.125f;
                v.y = ((c[mt][nt][2*h+1] - mu) * rs * sg[o+1] + sb[o+1]) * 0.125f;
                *(float2*)(rowp + o) = v;
            }
        }
    }
}

// ================= generic mma.sync tf32 GEMM (A k-major) =================
// EPI 0: raw store  Out[row*256 + o]   (row < mvalid)
// EPI 1: BN + transposed store Out[(z*256 + o)*NPOS + row]
template<int EPI>
__global__ __launch_bounds__(256, 2)
void mma_gemm_kernel(const float* __restrict__ A, const float* __restrict__ B,
                     float* __restrict__ Out, const float* __restrict__ p1,
                     const float* __restrict__ p2, int mvalid, int batchStride) {
    extern __shared__ uint32_t sm[];        // As[128*36] ++ Bs[128*36]
    uint32_t* As = sm;
    uint32_t* Bs = sm + 128 * 36;
    __shared__ float sp1[256], sp2[256];

    int tid = threadIdx.x;
    int wid = tid >> 5;
    int lane = tid & 31;
    int q = lane >> 2, tq = lane & 3;
    int wm = wid >> 2, wn = wid & 3;
    int z = blockIdx.z;
    int m0 = blockIdx.x * 128;
    int n0 = blockIdx.y * 128;
    const float* Ab = A + (size_t)z * batchStride;

    if (EPI == 1) { sp1[tid] = p1[tid] * rsqrtf(1.f + 1e-5f); sp2[tid] = p2[tid]; }

    float c[4][4][4];
#pragma unroll
    for (int mt = 0; mt < 4; mt++)
#pragma unroll
        for (int nt = 0; nt < 4; nt++)
#pragma unroll
            for (int i = 0; i < 4; i++) c[mt][nt][i] = 0.f;

    for (int ck = 0; ck < 8; ck++) {
        __syncthreads();
#pragma unroll
        for (int t = 0; t < 4; t++) {
            int idx = tid + t * 256;
            int row = idx >> 3, c4 = idx & 7;
            int ga = min(m0 + row, mvalid - 1);
            float4 va = *(const float4*)(Ab + (size_t)ga * DIMC + ck * 32 + c4 * 4);
            float4 vb = *(const float4*)(B + (size_t)(n0 + row) * DIMC + ck * 32 + c4 * 4);
            uint32_t* ap = As + row * 36 + c4 * 4;
            ap[0] = f2tf32(va.x); ap[1] = f2tf32(va.y); ap[2] = f2tf32(va.z); ap[3] = f2tf32(va.w);
            uint32_t* bp = Bs + row * 36 + c4 * 4;
            bp[0] = f2tf32(vb.x); bp[1] = f2tf32(vb.y); bp[2] = f2tf32(vb.z); bp[3] = f2tf32(vb.w);
        }
        __syncthreads();
#pragma unroll
        for (int ks = 0; ks < 4; ks++) {
            int k0 = ks * 8;
            uint32_t a[4][4];
#pragma unroll
            for (int mt = 0; mt < 4; mt++) {
                int r = wm * 64 + mt * 16 + q;
                a[mt][0] = As[r * 36 + k0 + tq];
                a[mt][1] = As[(r + 8) * 36 + k0 + tq];
                a[mt][2] = As[r * 36 + k0 + tq + 4];
                a[mt][3] = As[(r + 8) * 36 + k0 + tq + 4];
            }
            uint32_t b[4][2];
#pragma unroll
            for (int nt = 0; nt < 4; nt++) {
                int nn = wn * 32 + nt * 8 + q;
                b[nt][0] = Bs[nn * 36 + k0 + tq];
                b[nt][1] = Bs[nn * 36 + k0 + tq + 4];
            }
#pragma unroll
            for (int mt = 0; mt < 4; mt++)
#pragma unroll
                for (int nt = 0; nt < 4; nt++) {
                    asm volatile(
                        "mma.sync.aligned.m16n8k8.row.col.f32.tf32.tf32.f32 "
                        "{%0,%1,%2,%3}, {%4,%5,%6,%7}, {%8,%9}, {%0,%1,%2,%3};"
                        : "+f"(c[mt][nt][0]), "+f"(c[mt][nt][1]),
                          "+f"(c[mt][nt][2]), "+f"(c[mt][nt][3])
                        : "r"(a[mt][0]), "r"(a[mt][1]), "r"(a[mt][2]), "r"(a[mt][3]),
                          "r"(b[nt][0]), "r"(b[nt][1]));
                }
        }
    }

#pragma unroll
    for (int mt = 0; mt < 4; mt++) {
        int r0 = m0 + wm * 64 + mt * 16 + q;
#pragma unroll
        for (int nt = 0; nt < 4; nt++) {
            int o0 = n0 + wn * 32 + nt * 8 + 2 * tq;
            if (EPI == 0) {
                if (r0 < mvalid) {
                    float2 v = make_float2(c[mt][nt][0], c[mt][nt][1]);
                    *(float2*)(Out + (size_t)(z * NPOS + r0) * DIMC + o0) = v;
                }
                if (r0 + 8 < mvalid) {
                    float2 v = make_float2(c[mt][nt][2], c[mt][nt][3]);
                    *(float2*)(Out + (size_t)(z * NPOS + r0 + 8) * DIMC + o0) = v;
                }
            } else {
                float s0 = sp1[o0],     h0 = sp2[o0];
                float s1 = sp1[o0 + 1], h1 = sp2[o0 + 1];
                float* base0 = Out + ((size_t)(z * DIMC + o0)) * NPOS;
                float* base1 = Out + ((size_t)(z * DIMC + o0 + 1)) * NPOS;
                base0[r0]     = c[mt][nt][0] * s0 + h0;
                base1[r0]     = c[mt][nt][1] * s1 + h1;
                base0[r0 + 8] = c[mt][nt][2] * s0 + h0;
                base1[r0 + 8] = c[mt][nt][3] * s1 + h1;
            }
        }
    }
}

// ---------------- LN for kf rows (196) ----------------
__global__ __launch_bounds__(256) void ln_k_kernel(const float* __restrict__ gk,
                                                   const float* __restrict__ bk) {
    int row = blockIdx.x * 8 + (threadIdx.x >> 5);
    if (row >= NB * 49) return;
    int lane = threadIdx.x & 31;
    const float* rp = g_kraw + (size_t)row * DIMC;
    float v[8], s = 0.f, s2 = 0.f;
#pragma unroll
    for (int i = 0; i < 8; i++) { float t = rp[lane + 32*i]; v[i] = t; s += t; s2 += t*t; }
#pragma unroll
    for (int o = 16; o >= 1; o >>= 1) {
        s  += __shfl_xor_sync(0xffffffffu, s,  o);
        s2 += __shfl_xor_sync(0xffffffffu, s2, o);
    }
    float mu = s * (1.f/DIMC);
    float var = s2 * (1.f/DIMC) - mu*mu;
    float rs = rsqrtf(var + 1e-6f);
    float* wp = g_kf + (size_t)row * DIMC;
#pragma unroll
    for (int i = 0; i < 8; i++) {
        int o = lane + 32*i;
        wp[o] = (v[i]-mu)*rs*gk[o] + bk[o];
    }
}

// ---------------- ctx 8x8 avg pool ----------------
__global__ void pool_kernel(const float* __restrict__ ctx) {
    int idx = blockIdx.x*256 + threadIdx.x;
    if (idx >= NB*49*DIMC) return;
    int c = idx & 255;
    int l = (idx >> 8) % 49;
    int b = idx / (49*256);
    int li = l / 7, lj = l % 7;
    const float* p = ctx + ((size_t)(b*DIMC + c)*56 + li*8)*56 + lj*8;
    float s = 0.f;
#pragma unroll
    for (int ii = 0; ii < 8; ii++)
#pragma unroll
        for (int jj = 0; jj < 8; jj++) s += p[ii*56 + jj];
    g_kctx[idx] = s * (1.f/64.f);
}

// ---------------- fold Wproj ----------------
__global__ void kfp_kernel(const float* __restrict__ Wproj) {
    int idx = blockIdx.x*256 + threadIdx.x;
    if (idx >= NB*NHEAD*HD*80) return;
    int m  = idx % 80;
    int c  = (idx / 80) & 63;
    int bg = idx / (80*64);
    int b  = bg >> 2, gg = bg & 3;
    float s = 0.f;
    if (m < 74) {
        const float* wp = Wproj + m*49;
        for (int l = 0; l < 49; l++)
            s += g_kf[(size_t)(b*49 + l)*DIMC + gg*HD + c] * wp[l];
    }
    g_kfp[idx] = s;
}

// ---------------- wgt GEMM + RPB + softmax ----------------
__global__ __launch_bounds__(256) void wgt_softmax_kernel(const float* __restrict__ rpb1,
                                                          const float* __restrict__ rpb2) {
    __shared__ float As[64][68];
    __shared__ float Bs[64][80];
    int n0 = blockIdx.x * 64;
    int gy = blockIdx.y;
    int b  = gy >> 2, g = gy & 3;
    int tid = threadIdx.x;
    {
        int r = tid >> 2, quad = tid & 3;
        const float* src = g_qt + ((size_t)(b*NPOS + n0 + r))*DIMC + g*HD + quad*16;
#pragma unroll
        for (int s = 0; s < 4; s++)
            *(float4*)(&As[r][quad*16 + s*4]) = *(const float4*)(src + s*4);
    }
    {
        const float4* src = (const float4*)(g_kfp + (size_t)gy * HD * 80);
        float4* dst = (float4*)(&Bs[0][0]);
        for (int idx = tid; idx < HD*80/4; idx += 256) dst[idx] = src[idx];
    }
    __syncthreads();
    int tx = tid & 15, ty = tid >> 4;
    float acc[4][5];
#pragma unroll
    for (int r = 0; r < 4; r++)
#pragma unroll
        for (int j = 0; j < 5; j++) acc[r][j] = 0.f;
#pragma unroll
    for (int c = 0; c < 64; c++) {
        float ar[4], br[5];
#pragma unroll
        for (int r = 0; r < 4; r++) ar[r] = As[ty*4+r][c];
#pragma unroll
        for (int j = 0; j < 5; j++) br[j] = Bs[c][tx*5+j];
#pragma unroll
        for (int r = 0; r < 4; r++)
#pragma unroll
            for (int j = 0; j < 5; j++) acc[r][j] += ar[r]*br[j];
    }
    const float* rpb = (g < 2) ? (rpb1 + g*81) : (rpb2 + (g-2)*169);
#pragma unroll
    for (int r = 0; r < 4; r++) {
        int n = n0 + ty*4 + r;
        int i = n >> 6, j = n & 63;
        float vals[5];
        int   taps[5];
        bool  ok[5];
        if (g < 2) {
            int si = min(max(i-2,0),HH-5), sj = min(max(j-2,0),WW-5);
            int bi = 4 - (i - si), bj = 4 - (j - sj);
#pragma unroll
            for (int j5 = 0; j5 < 5; j5++) {
                int m = tx*5 + j5;
                bool v = (m < 25);
                int p = m/5, qq = m - p*5;
                ok[j5] = v; taps[j5] = m;
                vals[j5] = v ? acc[r][j5] + rpb[(bi+p)*9 + bj + qq] : -1e30f;
            }
        } else {
            int si = min(max(i-3,0),HH-7), sj = min(max(j-3,0),WW-7);
            int bi = 6 - (i - si), bj = 6 - (j - sj);
#pragma unroll
            for (int j5 = 0; j5 < 5; j5++) {
                int m = tx*5 + j5;
                int tap = m - 25;
                bool v = (m >= 25) && (m < 74);
                int p = tap/7, qq = tap - p*7;
                ok[j5] = v; taps[j5] = tap;
                vals[j5] = v ? acc[r][j5] + rpb[(bi+p)*13 + bj + qq] : -1e30f;
            }
        }
        float mx = vals[0];
#pragma unroll
        for (int j5 = 1; j5 < 5; j5++) mx = fmaxf(mx, vals[j5]);
#pragma unroll
        for (int o = 8; o >= 1; o >>= 1) mx = fmaxf(mx, __shfl_xor_sync(0xffffffffu, mx, o));
        float sum = 0.f;
#pragma unroll
        for (int j5 = 0; j5 < 5; j5++) {
            float e = ok[j5] ? __expf(vals[j5]-mx) : 0.f;
            vals[j5] = e; sum += e;
        }
#pragma unroll
        for (int o = 8; o >= 1; o >>= 1) sum += __shfl_xor_sync(0xffffffffu, sum, o);
        float inv = 1.f / sum;
        float* arow = g_attn + ((size_t)(gy*NPOS + n))*52;
#pragma unroll
        for (int j5 = 0; j5 < 5; j5++)
            if (ok[j5]) arow[taps[j5]] = vals[j5]*inv;
    }
}

// ---------------- neighborhood AV ----------------
template<int KK>
__global__ __launch_bounds__(256) void av_kernel(const float* __restrict__ x, int gbase) {
    const int HALO = 8 + KK - 1;
    extern __shared__ float vs[];
    int ti0 = (blockIdx.x >> 3) * 8, tj0 = (blockIdx.x & 7) * 8;
    int g = gbase + blockIdx.y;
    int b = blockIdx.z;
    int hbi = min(max(ti0 - KK/2, 0), HH - HALO);
    int hbj = min(max(tj0 - KK/2, 0), WW - HALO);
    const float* xb = x + (size_t)(b*DIMC + g*HD)*NPOS;
    for (int idx = threadIdx.x; idx < HALO*HALO*HD; idx += 256) {
        int c  = idx / (HALO*HALO);
        int rr = idx - c*HALO*HALO;
        int ri = rr / HALO, rj = rr - ri*HALO;
        vs[rr*68 + c] = xb[(size_t)c*NPOS + (hbi+ri)*WW + hbj + rj];
    }
    __syncthreads();
    int t = threadIdx.x;
    int pos = t >> 2, cg = t & 3;
    int i = ti0 + (pos >> 3), j = tj0 + (pos & 7);
    int n = i*WW + j;
    int si = min(max(i - KK/2, 0), HH-KK) - hbi;
    int sj = min(max(j - KK/2, 0), WW-KK) - hbj;
    const float* arow = g_attn + ((size_t)((b*NHEAD+g)*NPOS + n))*52;
    float4 a0 = make_float4(0,0,0,0), a1 = a0, a2 = a0, a3 = a0;
#pragma unroll
    for (int p = 0; p < KK; p++) {
#pragma unroll
        for (int qq = 0; qq < KK; qq++) {
            float a = __ldg(arow + p*KK + qq);
            const float4* vp = reinterpret_cast<const float4*>(&vs[((si+p)*HALO + sj+qq)*68 + cg*16]);
            float4 v0 = vp[0], v1 = vp[1], v2 = vp[2], v3 = vp[3];
            a0.x += a*v0.x; a0.y += a*v0.y; a0.z += a*v0.z; a0.w += a*v0.w;
            a1.x += a*v1.x; a1.y += a*v1.y; a1.z += a*v1.z; a1.w += a*v1.w;
            a2.x += a*v2.x; a2.y += a*v2.y; a2.z += a*v2.z; a2.w += a*v2.w;
            a3.x += a*v3.x; a3.y += a*v3.y; a3.z += a*v3.z; a3.w += a*v3.w;
        }
    }
    float* op = g_mid + ((size_t)(b*NPOS + n))*DIMC + g*HD + cg*16;
    ((float4*)op)[0] = a0; ((float4*)op)[1] = a1; ((float4*)op)[2] = a2; ((float4*)op)[3] = a3;
}

extern "C" void kernel_launch(void* const* d_in, const int* in_sizes, int n_in,
                              void* d_out, int out_size) {
    const float* x     = (const float*)d_in[0];
    const float* ctx   = (const float*)d_in[1];
    const float* Wq    = (const float*)d_in[2];
    const float* gq    = (const float*)d_in[3];
    const float* bq    = (const float*)d_in[4];
    const float* Wk    = (const float*)d_in[5];
    const float* gk    = (const float*)d_in[6];
    const float* bk    = (const float*)d_in[7];
    const float* Wproj = (const float*)d_in[8];
    const float* rpb1  = (const float*)d_in[9];
    const float* rpb2  = (const float*)d_in[10];
    const float* Wdy   = (const float*)d_in[11];
    const float* bn_g  = (const float*)d_in[12];
    const float* bn_b  = (const float*)d_in[13];
    float* out = (float*)d_out;

    const int GSMEM  = 2 * 128 * 36 * 4;                 // 36864
    const int G1SMEM = (32 * ASTR + 256 * 36) * 4;       // 54272
    cudaFuncSetAttribute(av_kernel<7>, cudaFuncAttributeMaxDynamicSharedMemorySize, 14*14*68*4);
    cudaFuncSetAttribute(gemm1_ln_kernel, cudaFuncAttributeMaxDynamicSharedMemorySize, G1SMEM);
    cudaFuncSetAttribute(mma_gemm_kernel<0>, cudaFuncAttributeMaxDynamicSharedMemorySize, GSMEM);
    cudaFuncSetAttribute(mma_gemm_kernel<1>, cudaFuncAttributeMaxDynamicSharedMemorySize, GSMEM);

    static float *p_kctx = nullptr, *p_kraw = nullptr, *p_mid = nullptr;
    if (!p_kctx) {
        cudaGetSymbolAddress((void**)&p_kctx, g_kctx);
        cudaGetSymbolAddress((void**)&p_kraw, g_kraw);
        cudaGetSymbolAddress((void**)&p_mid,  g_mid);
    }

    pool_kernel<<<(NB*49*DIMC + 255)/256, 256>>>(ctx);
    gemm1_ln_kernel<<<dim3(32, 1, NB), 512, G1SMEM>>>(x, Wq, gq, bq);
    mma_gemm_kernel<0><<<dim3(2, 2, 1), 256, GSMEM>>>(p_kctx, Wk, p_kraw, nullptr, nullptr, NB*49, 0);
    ln_k_kernel<<<25, 256>>>(gk, bk);
    kfp_kernel<<<(NB*NHEAD*HD*80 + 255)/256, 256>>>(Wproj);
    wgt_softmax_kernel<<<dim3(64, 16), 256>>>(rpb1, rpb2);
    av_kernel<5><<<dim3(64, 2, NB), 256, 12*12*68*4>>>(x, 0);
    av_kernel<7><<<dim3(64, 2, NB), 256, 14*14*68*4>>>(x, 2);
    mma_gemm_kernel<1><<<dim3(32, 2, NB), 256, GSMEM>>>(p_mid, Wdy, out, bn_g, bn_b, NPOS, NPOS*DIMC);
}

// round 7
// speedup vs baseline: 1.7122x; 1.1506x over previous
#include <cuda_runtime.h>
#include <cstdint>
#include <math.h>

#define NB 4
#define DIMC 256
#define HH 64
#define WW 64
#define NPOS (HH*WW)
#define NHEAD 4
#define HD 64

// ---------------- scratch ----------------
__device__ float g_qt[NB*NPOS*DIMC];         // LN(q)*scale [b][n][o]
__device__ float g_kctx[NB*49*DIMC];         // pooled ctx [row=(b*49+l)][c]
__device__ float g_kraw[256*DIMC];           // Wk@kctx raw (196 rows used)
__device__ float g_kmu[256], g_krs[256];     // per-row LN stats for kraw
__device__ float g_kfp[NB*NHEAD*80*64];      // folded proj [bg][m<74 pad80][c]
__device__ float g_attn[NB*NHEAD*NPOS*52];   // softmaxed attn
__device__ float g_mid[NB*NPOS*DIMC];        // AV out [b][n][c]

__device__ __forceinline__ uint32_t f2tf32(float f) {
    uint32_t r; asm("cvt.rna.tf32.f32 %0, %1;" : "=r"(r) : "f"(f)); return r;
}

// ================= gemm1 + fused LN =================
#define ASTR 136
__global__ __launch_bounds__(512, 1)
void gemm1_ln_kernel(const float* __restrict__ x, const float* __restrict__ Wq,
                     const float* __restrict__ gq, const float* __restrict__ bq) {
    extern __shared__ uint32_t sm[];                 // As2[32*ASTR] ++ Bs[256*36]
    uint32_t* As2 = sm;
    uint32_t* Bs  = sm + 32 * ASTR;
    __shared__ float red_s[128][9];
    __shared__ float red_s2[128][9];
    __shared__ float sg[256], sb[256];

    int tid  = threadIdx.x;
    int wid  = tid >> 5, lane = tid & 31;
    int q    = lane >> 2, tq = lane & 3;
    int wm   = wid >> 3, wn = wid & 7;               // 2 x 8
    int z    = blockIdx.z;
    int m0   = blockIdx.x * 128;
    const float* xb = x + (size_t)z * DIMC * NPOS;

    if (tid < 256) { sg[tid] = gq[tid]; sb[tid] = bq[tid]; }

    float c[4][4][4];
#pragma unroll
    for (int mt = 0; mt < 4; mt++)
#pragma unroll
        for (int nt = 0; nt < 4; nt++)
#pragma unroll
            for (int i = 0; i < 4; i++) c[mt][nt][i] = 0.f;

    for (int ck = 0; ck < 8; ck++) {
        __syncthreads();
#pragma unroll
        for (int it = 0; it < 2; it++) {
            int slot = tid + it * 512;
            int cc = slot >> 5, n4 = slot & 31;
            float4 v = *(const float4*)(xb + (size_t)(ck * 32 + cc) * NPOS + m0 + n4 * 4);
            uint4 u = make_uint4(f2tf32(v.x), f2tf32(v.y), f2tf32(v.z), f2tf32(v.w));
            *(uint4*)(As2 + cc * ASTR + n4 * 4) = u;
        }
#pragma unroll
        for (int it = 0; it < 4; it++) {
            int slot = tid + it * 512;
            int row = slot >> 3, c4 = slot & 7;
            float4 v = *(const float4*)(Wq + (size_t)row * DIMC + ck * 32 + c4 * 4);
            uint4 u = make_uint4(f2tf32(v.x), f2tf32(v.y), f2tf32(v.z), f2tf32(v.w));
            *(uint4*)(Bs + row * 36 + c4 * 4) = u;
        }
        __syncthreads();
#pragma unroll
        for (int ks = 0; ks < 4; ks++) {
            int k0 = ks * 8;
            uint32_t a[4][4];
#pragma unroll
            for (int mt = 0; mt < 4; mt++) {
                int r = wm * 64 + mt * 16 + q;
                a[mt][0] = As2[(k0 + tq) * ASTR + r];
                a[mt][1] = As2[(k0 + tq) * ASTR + r + 8];
                a[mt][2] = As2[(k0 + tq + 4) * ASTR + r];
                a[mt][3] = As2[(k0 + tq + 4) * ASTR + r + 8];
            }
            uint32_t b[4][2];
#pragma unroll
            for (int nt = 0; nt < 4; nt++) {
                int o = wn * 32 + nt * 8 + q;
                b[nt][0] = Bs[o * 36 + k0 + tq];
                b[nt][1] = Bs[o * 36 + k0 + tq + 4];
            }
#pragma unroll
            for (int mt = 0; mt < 4; mt++)
#pragma unroll
                for (int nt = 0; nt < 4; nt++) {
                    asm volatile(
                        "mma.sync.aligned.m16n8k8.row.col.f32.tf32.tf32.f32 "
                        "{%0,%1,%2,%3}, {%4,%5,%6,%7}, {%8,%9}, {%0,%1,%2,%3};"
                        : "+f"(c[mt][nt][0]), "+f"(c[mt][nt][1]),
                          "+f"(c[mt][nt][2]), "+f"(c[mt][nt][3])
                        : "r"(a[mt][0]), "r"(a[mt][1]), "r"(a[mt][2]), "r"(a[mt][3]),
                          "r"(b[nt][0]), "r"(b[nt][1]));
                }
        }
    }
#pragma unroll
    for (int mt = 0; mt < 4; mt++) {
#pragma unroll
        for (int h = 0; h < 2; h++) {
            float s = 0.f, s2 = 0.f;
#pragma unroll
            for (int nt = 0; nt < 4; nt++) {
                float v0 = c[mt][nt][2*h], v1 = c[mt][nt][2*h+1];
                s += v0 + v1; s2 += v0*v0 + v1*v1;
            }
            s  += __shfl_xor_sync(0xffffffffu, s, 1);
            s2 += __shfl_xor_sync(0xffffffffu, s2, 1);
            s  += __shfl_xor_sync(0xffffffffu, s, 2);
            s2 += __shfl_xor_sync(0xffffffffu, s2, 2);
            if (tq == 0) {
                int rl = wm * 64 + mt * 16 + q + h * 8;
                red_s[rl][wn] = s;
                red_s2[rl][wn] = s2;
            }
        }
    }
    __syncthreads();
    float* outb = g_qt + (size_t)blockIdx.z * NPOS * DIMC;
#pragma unroll
    for (int mt = 0; mt < 4; mt++) {
#pragma unroll
        for (int h = 0; h < 2; h++) {
            int rl = wm * 64 + mt * 16 + q + h * 8;
            float S = 0.f, S2 = 0.f;
#pragma unroll
            for (int w = 0; w < 8; w++) { S += red_s[rl][w]; S2 += red_s2[rl][w]; }
            float mu = S * (1.f/256.f);
            float var = S2 * (1.f/256.f) - mu * mu;
            float rs = rsqrtf(var + 1e-6f);
            float* rowp = outb + (size_t)(m0 + rl) * DIMC;
#pragma unroll
            for (int nt = 0; nt < 4; nt++) {
                int o = wn * 32 + nt * 8 + 2 * tq;
                float2 v;
                v.x = ((c[mt][nt][2*h]   - mu) * rs * sg[o]   + sb[o])   * 0.125f;
                v.y = ((c[mt][nt][2*h+1] - mu) * rs * sg[o+1] + sb[o+1]) * 0.125f;
                *(float2*)(rowp + o) = v;
            }
        }
    }
}

// ================= generic mma.sync tf32 GEMM (A k-major) =================
template<int EPI>
__global__ __launch_bounds__(256, 2)
void mma_gemm_kernel(const float* __restrict__ A, const float* __restrict__ B,
                     float* __restrict__ Out, const float* __restrict__ p1,
                     const float* __restrict__ p2, int mvalid, int batchStride) {
    extern __shared__ uint32_t sm[];
    uint32_t* As = sm;
    uint32_t* Bs = sm + 128 * 36;
    __shared__ float sp1[256], sp2[256];

    int tid = threadIdx.x;
    int wid = tid >> 5;
    int lane = tid & 31;
    int q = lane >> 2, tq = lane & 3;
    int wm = wid >> 2, wn = wid & 3;
    int z = blockIdx.z;
    int m0 = blockIdx.x * 128;
    int n0 = blockIdx.y * 128;
    const float* Ab = A + (size_t)z * batchStride;

    if (EPI == 1) { sp1[tid] = p1[tid] * rsqrtf(1.f + 1e-5f); sp2[tid] = p2[tid]; }

    float c[4][4][4];
#pragma unroll
    for (int mt = 0; mt < 4; mt++)
#pragma unroll
        for (int nt = 0; nt < 4; nt++)
#pragma unroll
            for (int i = 0; i < 4; i++) c[mt][nt][i] = 0.f;

    for (int ck = 0; ck < 8; ck++) {
        __syncthreads();
#pragma unroll
        for (int t = 0; t < 4; t++) {
            int idx = tid + t * 256;
            int row = idx >> 3, c4 = idx & 7;
            int ga = min(m0 + row, mvalid - 1);
            float4 va = *(const float4*)(Ab + (size_t)ga * DIMC + ck * 32 + c4 * 4);
            float4 vb = *(const float4*)(B + (size_t)(n0 + row) * DIMC + ck * 32 + c4 * 4);
            uint32_t* ap = As + row * 36 + c4 * 4;
            ap[0] = f2tf32(va.x); ap[1] = f2tf32(va.y); ap[2] = f2tf32(va.z); ap[3] = f2tf32(va.w);
            uint32_t* bp = Bs + row * 36 + c4 * 4;
            bp[0] = f2tf32(vb.x); bp[1] = f2tf32(vb.y); bp[2] = f2tf32(vb.z); bp[3] = f2tf32(vb.w);
        }
        __syncthreads();
#pragma unroll
        for (int ks = 0; ks < 4; ks++) {
            int k0 = ks * 4 * 2;
            uint32_t a[4][4];
#pragma unroll
            for (int mt = 0; mt < 4; mt++) {
                int r = wm * 64 + mt * 16 + q;
                a[mt][0] = As[r * 36 + k0 + tq];
                a[mt][1] = As[(r + 8) * 36 + k0 + tq];
                a[mt][2] = As[r * 36 + k0 + tq + 4];
                a[mt][3] = As[(r + 8) * 36 + k0 + tq + 4];
            }
            uint32_t b[4][2];
#pragma unroll
            for (int nt = 0; nt < 4; nt++) {
                int nn = wn * 32 + nt * 8 + q;
                b[nt][0] = Bs[nn * 36 + k0 + tq];
                b[nt][1] = Bs[nn * 36 + k0 + tq + 4];
            }
#pragma unroll
            for (int mt = 0; mt < 4; mt++)
#pragma unroll
                for (int nt = 0; nt < 4; nt++) {
                    asm volatile(
                        "mma.sync.aligned.m16n8k8.row.col.f32.tf32.tf32.f32 "
                        "{%0,%1,%2,%3}, {%4,%5,%6,%7}, {%8,%9}, {%0,%1,%2,%3};"
                        : "+f"(c[mt][nt][0]), "+f"(c[mt][nt][1]),
                          "+f"(c[mt][nt][2]), "+f"(c[mt][nt][3])
                        : "r"(a[mt][0]), "r"(a[mt][1]), "r"(a[mt][2]), "r"(a[mt][3]),
                          "r"(b[nt][0]), "r"(b[nt][1]));
                }
        }
    }

#pragma unroll
    for (int mt = 0; mt < 4; mt++) {
        int r0 = m0 + wm * 64 + mt * 16 + q;
#pragma unroll
        for (int nt = 0; nt < 4; nt++) {
            int o0 = n0 + wn * 32 + nt * 8 + 2 * tq;
            if (EPI == 0) {
                if (r0 < mvalid) {
                    float2 v = make_float2(c[mt][nt][0], c[mt][nt][1]);
                    *(float2*)(Out + (size_t)(z * NPOS + r0) * DIMC + o0) = v;
                }
                if (r0 + 8 < mvalid) {
                    float2 v = make_float2(c[mt][nt][2], c[mt][nt][3]);
                    *(float2*)(Out + (size_t)(z * NPOS + r0 + 8) * DIMC + o0) = v;
                }
            } else {
                float s0 = sp1[o0],     h0 = sp2[o0];
                float s1 = sp1[o0 + 1], h1 = sp2[o0 + 1];
                float* base0 = Out + ((size_t)(z * DIMC + o0)) * NPOS;
                float* base1 = Out + ((size_t)(z * DIMC + o0 + 1)) * NPOS;
                base0[r0]     = c[mt][nt][0] * s0 + h0;
                base1[r0]     = c[mt][nt][1] * s1 + h1;
                base0[r0 + 8] = c[mt][nt][2] * s0 + h0;
                base1[r0 + 8] = c[mt][nt][3] * s1 + h1;
            }
        }
    }
}

// ---------------- ctx 8x8 avg pool (warp-per-channel) ----------------
__global__ __launch_bounds__(256) void pool_kernel(const float* __restrict__ ctx) {
    int l = blockIdx.x, b = blockIdx.y;
    int li = l / 7, lj = l % 7;
    int wid = threadIdx.x >> 5, lane = threadIdx.x & 31;
    int ri = lane >> 2, rj = lane & 3;
    const float* base = ctx + (size_t)b * DIMC * 3136 + (li * 8 + ri) * 56 + lj * 8 + rj * 2;
    float* outp = g_kctx + (size_t)(b * 49 + l) * DIMC;
#pragma unroll
    for (int k = 0; k < 32; k++) {
        int c = wid * 32 + k;
        float2 v = *(const float2*)(base + (size_t)c * 3136);
        float s = v.x + v.y;
#pragma unroll
        for (int o = 16; o >= 1; o >>= 1) s += __shfl_xor_sync(0xffffffffu, s, o);
        if (lane == 0) outp[c] = s * (1.f / 64.f);
    }
}

// ---------------- LN stats for kraw rows (196) ----------------
__global__ __launch_bounds__(256) void kstats_kernel() {
    int row = blockIdx.x * 8 + (threadIdx.x >> 5);
    if (row >= NB * 49) return;
    int lane = threadIdx.x & 31;
    const float* rp = g_kraw + (size_t)row * DIMC;
    float s = 0.f, s2 = 0.f;
#pragma unroll
    for (int i = 0; i < 8; i++) { float t = rp[lane + 32*i]; s += t; s2 += t*t; }
#pragma unroll
    for (int o = 16; o >= 1; o >>= 1) {
        s  += __shfl_xor_sync(0xffffffffu, s,  o);
        s2 += __shfl_xor_sync(0xffffffffu, s2, o);
    }
    if (lane == 0) {
        float mu = s * (1.f/DIMC);
        float var = s2 * (1.f/DIMC) - mu*mu;
        g_kmu[row] = mu;
        g_krs[row] = rsqrtf(var + 1e-6f);
    }
}

// ---------------- fold Wproj with inline LN -> kfp[bg][m][c] ----------------
__global__ void kfp_kernel(const float* __restrict__ Wproj,
                           const float* __restrict__ gk, const float* __restrict__ bk) {
    int idx = blockIdx.x*256 + threadIdx.x;
    if (idx >= NB*NHEAD*80*64) return;
    int c  = idx & 63;
    int m  = (idx >> 6) % 80;
    int bg = idx / (80*64);
    int b  = bg >> 2, gg = bg & 3;
    float s = 0.f;
    if (m < 74) {
        const float* wp = Wproj + m*49;
        float sw = 0.f;
        for (int l = 0; l < 49; l++) {
            int row = b*49 + l;
            float w = wp[l];
            s += (g_kraw[(size_t)row*DIMC + gg*HD + c] - g_kmu[row]) * g_krs[row] * w;
            sw += w;
        }
        s = s * gk[gg*HD + c] + sw * bk[gg*HD + c];
    }
    g_kfp[idx] = s;
}

// ---------------- wgt mma GEMM [128 x 80 x 64] + RPB + softmax ----------------
__global__ __launch_bounds__(256)
void wgt_mma_kernel(const float* __restrict__ rpb1, const float* __restrict__ rpb2) {
    extern __shared__ char smc[];
    uint32_t* As = (uint32_t*)smc;                 // [128][68]
    uint32_t* Bs = As + 128 * 68;                  // [80][68]
    float*    Wg = (float*)smc;                    // [128][85]  (aliases As/Bs after mma)
    __shared__ float srpb[169];

    int tid = threadIdx.x;
    int wid = tid >> 5, lane = tid & 31;
    int q = lane >> 2, tq = lane & 3;
    int wm = wid >> 1, wn = wid & 1;               // 4m x 2n
    int m0 = blockIdx.x * 128;
    int gy = blockIdx.y;
    int b  = gy >> 2, g = gy & 3;

    // rpb to smem
    if (g < 2) { if (tid < 81) srpb[tid] = rpb1[g*81 + tid]; }
    else       { if (tid < 169) srpb[tid] = rpb2[(g-2)*169 + tid]; }

    // load A: qt rows, head slice (convert tf32)
    const float* Abase = g_qt + ((size_t)(b * NPOS + m0)) * DIMC + g * HD;
#pragma unroll
    for (int it = 0; it < 8; it++) {
        int slot = tid + it * 256;                 // 2048 float4
        int row = slot >> 4, c4 = slot & 15;
        float4 v = *(const float4*)(Abase + (size_t)row * DIMC + c4 * 4);
        uint4 u = make_uint4(f2tf32(v.x), f2tf32(v.y), f2tf32(v.z), f2tf32(v.w));
        *(uint4*)(As + row * 68 + c4 * 4) = u;
    }
    // load B: kfp[bg][m][c]
    const float* Bbase = g_kfp + (size_t)gy * 80 * 64;
#pragma unroll
    for (int it = 0; it < 5; it++) {
        int slot = tid + it * 256;                 // 1280 float4
        int mrow = slot >> 4, c4 = slot & 15;
        float4 v = *(const float4*)(Bbase + (size_t)mrow * 64 + c4 * 4);
        uint4 u = make_uint4(f2tf32(v.x), f2tf32(v.y), f2tf32(v.z), f2tf32(v.w));
        *(uint4*)(Bs + mrow * 68 + c4 * 4) = u;
    }
    __syncthreads();

    float c[2][5][4];
#pragma unroll
    for (int mt = 0; mt < 2; mt++)
#pragma unroll
        for (int nt = 0; nt < 5; nt++)
#pragma unroll
            for (int i = 0; i < 4; i++) c[mt][nt][i] = 0.f;

#pragma unroll
    for (int ks = 0; ks < 8; ks++) {
        int k0 = ks * 8;
        uint32_t a[2][4];
#pragma unroll
        for (int mt = 0; mt < 2; mt++) {
            int r = wm * 32 + mt * 16 + q;
            a[mt][0] = As[r * 68 + k0 + tq];
            a[mt][1] = As[(r + 8) * 68 + k0 + tq];
            a[mt][2] = As[r * 68 + k0 + tq + 4];
            a[mt][3] = As[(r + 8) * 68 + k0 + tq + 4];
        }
        uint32_t bfr[5][2];
#pragma unroll
        for (int nt = 0; nt < 5; nt++) {
            int col = wn * 40 + nt * 8 + q;
            bfr[nt][0] = Bs[col * 68 + k0 + tq];
            bfr[nt][1] = Bs[col * 68 + k0 + tq + 4];
        }
#pragma unroll
        for (int mt = 0; mt < 2; mt++)
#pragma unroll
            for (int nt = 0; nt < 5; nt++) {
                asm volatile(
                    "mma.sync.aligned.m16n8k8.row.col.f32.tf32.tf32.f32 "
                    "{%0,%1,%2,%3}, {%4,%5,%6,%7}, {%8,%9}, {%0,%1,%2,%3};"
                    : "+f"(c[mt][nt][0]), "+f"(c[mt][nt][1]),
                      "+f"(c[mt][nt][2]), "+f"(c[mt][nt][3])
                    : "r"(a[mt][0]), "r"(a[mt][1]), "r"(a[mt][2]), "r"(a[mt][3]),
                      "r"(bfr[nt][0]), "r"(bfr[nt][1]));
            }
    }
    __syncthreads();   // done reading As/Bs; Wg aliases them

    // spill accumulators to smem [128][85]
#pragma unroll
    for (int mt = 0; mt < 2; mt++) {
        int r = wm * 32 + mt * 16 + q;
#pragma unroll
        for (int nt = 0; nt < 5; nt++) {
            int col = wn * 40 + nt * 8 + 2 * tq;
            Wg[r * 85 + col]       = c[mt][nt][0];
            Wg[r * 85 + col + 1]   = c[mt][nt][1];
            Wg[(r+8) * 85 + col]   = c[mt][nt][2];
            Wg[(r+8) * 85 + col+1] = c[mt][nt][3];
        }
    }
    __syncthreads();

    // per-row softmax (threads 0..127)
    if (tid < 128) {
        int n = m0 + tid;
        int i = n >> 6, j = n & 63;
        float* wrow = Wg + tid * 85;
        float* arow = g_attn + ((size_t)(gy * NPOS + n)) * 52;
        if (g < 2) {
            int si = min(max(i-2,0),HH-5), sj = min(max(j-2,0),WW-5);
            int bi = 4 - (i - si), bj = 4 - (j - sj);
            float mx = -1e30f;
#pragma unroll
            for (int m = 0; m < 25; m++) {
                int p = m / 5, qq = m - p*5;
                float v = wrow[m] + srpb[(bi+p)*9 + bj + qq];
                wrow[m] = v;
                mx = fmaxf(mx, v);
            }
            float sum = 0.f;
#pragma unroll
            for (int m = 0; m < 25; m++) {
                float e = __expf(wrow[m] - mx);
                wrow[m] = e; sum += e;
            }
            float inv = 1.f / sum;
#pragma unroll
            for (int m = 0; m < 25; m++) arow[m] = wrow[m] * inv;
        } else {
            int si = min(max(i-3,0),HH-7), sj = min(max(j-3,0),WW-7);
            int bi = 6 - (i - si), bj = 6 - (j - sj);
            float mx = -1e30f;
#pragma unroll
            for (int t = 0; t < 49; t++) {
                int p = t / 7, qq = t - p*7;
                float v = wrow[25 + t] + srpb[(bi+p)*13 + bj + qq];
                wrow[25 + t] = v;
                mx = fmaxf(mx, v);
            }
            float sum = 0.f;
#pragma unroll
            for (int t = 0; t < 49; t++) {
                float e = __expf(wrow[25 + t] - mx);
                wrow[25 + t] = e; sum += e;
            }
            float inv = 1.f / sum;
#pragma unroll
            for (int t = 0; t < 49; t++) arow[t] = wrow[25 + t] * inv;
        }
    }
}

// ---------------- neighborhood AV (merged 5/7) ----------------
template<int KK>
__device__ __forceinline__ void av_body(const float* __restrict__ x, int g, float* vs) {
    const int HALO = 8 + KK - 1;
    int ti0 = (blockIdx.x >> 3) * 8, tj0 = (blockIdx.x & 7) * 8;
    int b = blockIdx.z;
    int hbi = min(max(ti0 - KK/2, 0), HH - HALO);
    int hbj = min(max(tj0 - KK/2, 0), WW - HALO);
    const float* xb = x + (size_t)(b*DIMC + g*HD)*NPOS;
    for (int idx = threadIdx.x; idx < HALO*HALO*HD; idx += 256) {
        int c  = idx / (HALO*HALO);
        int rr = idx - c*HALO*HALO;
        int ri = rr / HALO, rj = rr - ri*HALO;
        vs[rr*68 + c] = xb[(size_t)c*NPOS + (hbi+ri)*WW + hbj + rj];
    }
    __syncthreads();
    int t = threadIdx.x;
    int pos = t >> 2, cg = t & 3;
    int i = ti0 + (pos >> 3), j = tj0 + (pos & 7);
    int n = i*WW + j;
    int si = min(max(i - KK/2, 0), HH-KK) - hbi;
    int sj = min(max(j - KK/2, 0), WW-KK) - hbj;
    const float* arow = g_attn + ((size_t)((b*NHEAD+g)*NPOS + n))*52;
    float4 a0 = make_float4(0,0,0,0), a1 = a0, a2 = a0, a3 = a0;
#pragma unroll
    for (int p = 0; p < KK; p++) {
#pragma unroll
        for (int qq = 0; qq < KK; qq++) {
            float a = __ldg(arow + p*KK + qq);
            const float4* vp = reinterpret_cast<const float4*>(&vs[((si+p)*HALO + sj+qq)*68 + cg*16]);
            float4 v0 = vp[0], v1 = vp[1], v2 = vp[2], v3 = vp[3];
            a0.x += a*v0.x; a0.y += a*v0.y; a0.z += a*v0.z; a0.w += a*v0.w;
            a1.x += a*v1.x; a1.y += a*v1.y; a1.z += a*v1.z; a1.w += a*v1.w;
            a2.x += a*v2.x; a2.y += a*v2.y; a2.z += a*v2.z; a2.w += a*v2.w;
            a3.x += a*v3.x; a3.y += a*v3.y; a3.z += a*v3.z; a3.w += a*v3.w;
        }
    }
    float* op = g_mid + ((size_t)(b*NPOS + n))*DIMC + g*HD + cg*16;
    ((float4*)op)[0] = a0; ((float4*)op)[1] = a1; ((float4*)op)[2] = a2; ((float4*)op)[3] = a3;
}

__global__ __launch_bounds__(256) void av_all_kernel(const float* __restrict__ x) {
    extern __shared__ float vs[];
    int g = blockIdx.y;
    if (g < 2) av_body<5>(x, g, vs);
    else       av_body<7>(x, g, vs);
}

extern "C" void kernel_launch(void* const* d_in, const int* in_sizes, int n_in,
                              void* d_out, int out_size) {
    const float* x     = (const float*)d_in[0];
    const float* ctx   = (const float*)d_in[1];
    const float* Wq    = (const float*)d_in[2];
    const float* gq    = (const float*)d_in[3];
    const float* bq    = (const float*)d_in[4];
    const float* Wk    = (const float*)d_in[5];
    const float* gk    = (const float*)d_in[6];
    const float* bk    = (const float*)d_in[7];
    const float* Wproj = (const float*)d_in[8];
    const float* rpb1  = (const float*)d_in[9];
    const float* rpb2  = (const float*)d_in[10];
    const float* Wdy   = (const float*)d_in[11];
    const float* bn_g  = (const float*)d_in[12];
    const float* bn_b  = (const float*)d_in[13];
    float* out = (float*)d_out;

    const int GSMEM   = 2 * 128 * 36 * 4;                 // 36864
    const int G1SMEM  = (32 * ASTR + 256 * 36) * 4;       // 54272
    const int WGSMEM  = (128 * 68 + 80 * 68) * 4;         // 56576
    const int AVSMEM  = 14 * 14 * 68 * 4;                 // 53312
    cudaFuncSetAttribute(av_all_kernel, cudaFuncAttributeMaxDynamicSharedMemorySize, AVSMEM);
    cudaFuncSetAttribute(gemm1_ln_kernel, cudaFuncAttributeMaxDynamicSharedMemorySize, G1SMEM);
    cudaFuncSetAttribute(wgt_mma_kernel, cudaFuncAttributeMaxDynamicSharedMemorySize, WGSMEM);
    cudaFuncSetAttribute(mma_gemm_kernel<0>, cudaFuncAttributeMaxDynamicSharedMemorySize, GSMEM);
    cudaFuncSetAttribute(mma_gemm_kernel<1>, cudaFuncAttributeMaxDynamicSharedMemorySize, GSMEM);

    static float *p_kctx = nullptr, *p_kraw = nullptr, *p_mid = nullptr;
    if (!p_kctx) {
        cudaGetSymbolAddress((void**)&p_kctx, g_kctx);
        cudaGetSymbolAddress((void**)&p_kraw, g_kraw);
        cudaGetSymbolAddress((void**)&p_mid,  g_mid);
    }

    pool_kernel<<<dim3(49, NB), 256>>>(ctx);
    mma_gemm_kernel<0><<<dim3(2, 2, 1), 256, GSMEM>>>(p_kctx, Wk, p_kraw, nullptr, nullptr, NB*49, 0);
    kstats_kernel<<<25, 256>>>();
    kfp_kernel<<<(NB*NHEAD*80*64 + 255)/256, 256>>>(Wproj, gk, bk);
    gemm1_ln_kernel<<<dim3(32, 1, NB), 512, G1SMEM>>>(x, Wq, gq, bq);
    wgt_mma_kernel<<<dim3(32, 16), 256, WGSMEM>>>(rpb1, rpb2);
    av_all_kernel<<<dim3(64, 4, NB), 256, AVSMEM>>>(x);
    mma_gemm_kernel<1><<<dim3(32, 2, NB), 256, GSMEM>>>(p_mid, Wdy, out, bn_g, bn_b, NPOS, NPOS*DIMC);
}

// round 10
// speedup vs baseline: 1.7702x; 1.0339x over previous
#include <cuda_runtime.h>
#include <cstdint>
#include <math.h>

#define NB 4
#define DIMC 256
#define HH 64
#define WW 64
#define NPOS (HH*WW)
#define NHEAD 4
#define HD 64

// ---------------- scratch ----------------
__device__ float g_qt[NB*NPOS*DIMC];         // LN(q)*scale [b][n][o]
__device__ float g_kctx[NB*49*DIMC];         // pooled ctx [row=(b*49+l)][c]
__device__ float g_kraw[256*DIMC];           // Wk@kctx raw (196 rows used)
__device__ float g_kfp[NB*NHEAD*80*64];      // folded proj [bg][m<74 pad80][c]
__device__ float g_attn[NB*NHEAD*NPOS*52];   // softmaxed attn
__device__ float g_mid[NB*NPOS*DIMC];        // AV out [b][n][c]

__device__ __forceinline__ uint32_t f2tf32(float f) {
    uint32_t r; asm("cvt.rna.tf32.f32 %0, %1;" : "=r"(r) : "f"(f)); return r;
}

// ================= gemm1 + fused LN =================
#define ASTR 136
__global__ __launch_bounds__(512, 1)
void gemm1_ln_kernel(const float* __restrict__ x, const float* __restrict__ Wq,
                     const float* __restrict__ gq, const float* __restrict__ bq) {
    extern __shared__ uint32_t sm[];                 // As2[32*ASTR] ++ Bs[256*36]
    uint32_t* As2 = sm;
    uint32_t* Bs  = sm + 32 * ASTR;
    __shared__ float red_s[128][9];
    __shared__ float red_s2[128][9];
    __shared__ float sg[256], sb[256];

    int tid  = threadIdx.x;
    int wid  = tid >> 5, lane = tid & 31;
    int q    = lane >> 2, tq = lane & 3;
    int wm   = wid >> 3, wn = wid & 7;               // 2 x 8
    int z    = blockIdx.z;
    int m0   = blockIdx.x * 128;
    const float* xb = x + (size_t)z * DIMC * NPOS;

    if (tid < 256) { sg[tid] = gq[tid]; sb[tid] = bq[tid]; }

    float c[4][4][4];
#pragma unroll
    for (int mt = 0; mt < 4; mt++)
#pragma unroll
        for (int nt = 0; nt < 4; nt++)
#pragma unroll
            for (int i = 0; i < 4; i++) c[mt][nt][i] = 0.f;

    for (int ck = 0; ck < 8; ck++) {
        __syncthreads();
#pragma unroll
        for (int it = 0; it < 2; it++) {
            int slot = tid + it * 512;
            int cc = slot >> 5, n4 = slot & 31;
            float4 v = *(const float4*)(xb + (size_t)(ck * 32 + cc) * NPOS + m0 + n4 * 4);
            uint4 u = make_uint4(f2tf32(v.x), f2tf32(v.y), f2tf32(v.z), f2tf32(v.w));
            *(uint4*)(As2 + cc * ASTR + n4 * 4) = u;
        }
#pragma unroll
        for (int it = 0; it < 4; it++) {
            int slot = tid + it * 512;
            int row = slot >> 3, c4 = slot & 7;
            float4 v = *(const float4*)(Wq + (size_t)row * DIMC + ck * 32 + c4 * 4);
            uint4 u = make_uint4(f2tf32(v.x), f2tf32(v.y), f2tf32(v.z), f2tf32(v.w));
            *(uint4*)(Bs + row * 36 + c4 * 4) = u;
        }
        __syncthreads();
#pragma unroll
        for (int ks = 0; ks < 4; ks++) {
            int k0 = ks * 8;
            uint32_t a[4][4];
#pragma unroll
            for (int mt = 0; mt < 4; mt++) {
                int r = wm * 64 + mt * 16 + q;
                a[mt][0] = As2[(k0 + tq) * ASTR + r];
                a[mt][1] = As2[(k0 + tq) * ASTR + r + 8];
                a[mt][2] = As2[(k0 + tq + 4) * ASTR + r];
                a[mt][3] = As2[(k0 + tq + 4) * ASTR + r + 8];
            }
            uint32_t b[4][2];
#pragma unroll
            for (int nt = 0; nt < 4; nt++) {
                int o = wn * 32 + nt * 8 + q;
                b[nt][0] = Bs[o * 36 + k0 + tq];
                b[nt][1] = Bs[o * 36 + k0 + tq + 4];
            }
#pragma unroll
            for (int mt = 0; mt < 4; mt++)
#pragma unroll
                for (int nt = 0; nt < 4; nt++) {
                    asm volatile(
                        "mma.sync.aligned.m16n8k8.row.col.f32.tf32.tf32.f32 "
                        "{%0,%1,%2,%3}, {%4,%5,%6,%7}, {%8,%9}, {%0,%1,%2,%3};"
                        : "+f"(c[mt][nt][0]), "+f"(c[mt][nt][1]),
                          "+f"(c[mt][nt][2]), "+f"(c[mt][nt][3])
                        : "r"(a[mt][0]), "r"(a[mt][1]), "r"(a[mt][2]), "r"(a[mt][3]),
                          "r"(b[nt][0]), "r"(b[nt][1]));
                }
        }
    }
#pragma unroll
    for (int mt = 0; mt < 4; mt++) {
#pragma unroll
        for (int h = 0; h < 2; h++) {
            float s = 0.f, s2 = 0.f;
#pragma unroll
            for (int nt = 0; nt < 4; nt++) {
                float v0 = c[mt][nt][2*h], v1 = c[mt][nt][2*h+1];
                s += v0 + v1; s2 += v0*v0 + v1*v1;
            }
            s  += __shfl_xor_sync(0xffffffffu, s, 1);
            s2 += __shfl_xor_sync(0xffffffffu, s2, 1);
            s  += __shfl_xor_sync(0xffffffffu, s, 2);
            s2 += __shfl_xor_sync(0xffffffffu, s2, 2);
            if (tq == 0) {
                int rl = wm * 64 + mt * 16 + q + h * 8;
                red_s[rl][wn] = s;
                red_s2[rl][wn] = s2;
            }
        }
    }
    __syncthreads();
    float* outb = g_qt + (size_t)blockIdx.z * NPOS * DIMC;
#pragma unroll
    for (int mt = 0; mt < 4; mt++) {
#pragma unroll
        for (int h = 0; h < 2; h++) {
            int rl = wm * 64 + mt * 16 + q + h * 8;
            float S = 0.f, S2 = 0.f;
#pragma unroll
            for (int w = 0; w < 8; w++) { S += red_s[rl][w]; S2 += red_s2[rl][w]; }
            float mu = S * (1.f/256.f);
            float var = S2 * (1.f/256.f) - mu * mu;
            float rs = rsqrtf(var + 1e-6f);
            float* rowp = outb + (size_t)(m0 + rl) * DIMC;
#pragma unroll
            for (int nt = 0; nt < 4; nt++) {
                int o = wn * 32 + nt * 8 + 2 * tq;
                float2 v;
                v.x = ((c[mt][nt][2*h]   - mu) * rs * sg[o]   + sb[o])   * 0.125f;
                v.y = ((c[mt][nt][2*h+1] - mu) * rs * sg[o+1] + sb[o+1]) * 0.125f;
                *(float2*)(rowp + o) = v;
            }
        }
    }
}

// ================= generic mma.sync tf32 GEMM (A k-major) =================
template<int EPI>
__global__ __launch_bounds__(256, 2)
void mma_gemm_kernel(const float* __restrict__ A, const float* __restrict__ B,
                     float* __restrict__ Out, const float* __restrict__ p1,
                     const float* __restrict__ p2, int mvalid, int batchStride) {
    extern __shared__ uint32_t sm[];
    uint32_t* As = sm;
    uint32_t* Bs = sm + 128 * 36;
    __shared__ float sp1[256], sp2[256];

    int tid = threadIdx.x;
    int wid = tid >> 5;
    int lane = tid & 31;
    int q = lane >> 2, tq = lane & 3;
    int wm = wid >> 2, wn = wid & 3;
    int z = blockIdx.z;
    int m0 = blockIdx.x * 128;
    int n0 = blockIdx.y * 128;
    const float* Ab = A + (size_t)z * batchStride;

    if (EPI == 1) { sp1[tid] = p1[tid] * rsqrtf(1.f + 1e-5f); sp2[tid] = p2[tid]; }

    float c[4][4][4];
#pragma unroll
    for (int mt = 0; mt < 4; mt++)
#pragma unroll
        for (int nt = 0; nt < 4; nt++)
#pragma unroll
            for (int i = 0; i < 4; i++) c[mt][nt][i] = 0.f;

    for (int ck = 0; ck < 8; ck++) {
        __syncthreads();
#pragma unroll
        for (int t = 0; t < 4; t++) {
            int idx = tid + t * 256;
            int row = idx >> 3, c4 = idx & 7;
            int ga = min(m0 + row, mvalid - 1);
            float4 va = *(const float4*)(Ab + (size_t)ga * DIMC + ck * 32 + c4 * 4);
            float4 vb = *(const float4*)(B + (size_t)(n0 + row) * DIMC + ck * 32 + c4 * 4);
            uint32_t* ap = As + row * 36 + c4 * 4;
            ap[0] = f2tf32(va.x); ap[1] = f2tf32(va.y); ap[2] = f2tf32(va.z); ap[3] = f2tf32(va.w);
            uint32_t* bp = Bs + row * 36 + c4 * 4;
            bp[0] = f2tf32(vb.x); bp[1] = f2tf32(vb.y); bp[2] = f2tf32(vb.z); bp[3] = f2tf32(vb.w);
        }
        __syncthreads();
#pragma unroll
        for (int ks = 0; ks < 4; ks++) {
            int k0 = ks * 8;
            uint32_t a[4][4];
#pragma unroll
            for (int mt = 0; mt < 4; mt++) {
                int r = wm * 64 + mt * 16 + q;
                a[mt][0] = As[r * 36 + k0 + tq];
                a[mt][1] = As[(r + 8) * 36 + k0 + tq];
                a[mt][2] = As[r * 36 + k0 + tq + 4];
                a[mt][3] = As[(r + 8) * 36 + k0 + tq + 4];
            }
            uint32_t b[4][2];
#pragma unroll
            for (int nt = 0; nt < 4; nt++) {
                int nn = wn * 32 + nt * 8 + q;
                b[nt][0] = Bs[nn * 36 + k0 + tq];
                b[nt][1] = Bs[nn * 36 + k0 + tq + 4];
            }
#pragma unroll
            for (int mt = 0; mt < 4; mt++)
#pragma unroll
                for (int nt = 0; nt < 4; nt++) {
                    asm volatile(
                        "mma.sync.aligned.m16n8k8.row.col.f32.tf32.tf32.f32 "
                        "{%0,%1,%2,%3}, {%4,%5,%6,%7}, {%8,%9}, {%0,%1,%2,%3};"
                        : "+f"(c[mt][nt][0]), "+f"(c[mt][nt][1]),
                          "+f"(c[mt][nt][2]), "+f"(c[mt][nt][3])
                        : "r"(a[mt][0]), "r"(a[mt][1]), "r"(a[mt][2]), "r"(a[mt][3]),
                          "r"(b[nt][0]), "r"(b[nt][1]));
                }
        }
    }

#pragma unroll
    for (int mt = 0; mt < 4; mt++) {
        int r0 = m0 + wm * 64 + mt * 16 + q;
#pragma unroll
        for (int nt = 0; nt < 4; nt++) {
            int o0 = n0 + wn * 32 + nt * 8 + 2 * tq;
            if (EPI == 0) {
                if (r0 < mvalid) {
                    float2 v = make_float2(c[mt][nt][0], c[mt][nt][1]);
                    *(float2*)(Out + (size_t)(z * NPOS + r0) * DIMC + o0) = v;
                }
                if (r0 + 8 < mvalid) {
                    float2 v = make_float2(c[mt][nt][2], c[mt][nt][3]);
                    *(float2*)(Out + (size_t)(z * NPOS + r0 + 8) * DIMC + o0) = v;
                }
            } else {
                float s0 = sp1[o0],     h0 = sp2[o0];
                float s1 = sp1[o0 + 1], h1 = sp2[o0 + 1];
                float* base0 = Out + ((size_t)(z * DIMC + o0)) * NPOS;
                float* base1 = Out + ((size_t)(z * DIMC + o0 + 1)) * NPOS;
                base0[r0]     = c[mt][nt][0] * s0 + h0;
                base1[r0]     = c[mt][nt][1] * s1 + h1;
                base0[r0 + 8] = c[mt][nt][2] * s0 + h0;
                base1[r0 + 8] = c[mt][nt][3] * s1 + h1;
            }
        }
    }
}

// ---------------- ctx 8x8 avg pool (warp-per-channel) ----------------
__global__ __launch_bounds__(256) void pool_kernel(const float* __restrict__ ctx) {
    int l = blockIdx.x, b = blockIdx.y;
    int li = l / 7, lj = l % 7;
    int wid = threadIdx.x >> 5, lane = threadIdx.x & 31;
    int ri = lane >> 2, rj = lane & 3;
    const float* base = ctx + (size_t)b * DIMC * 3136 + (li * 8 + ri) * 56 + lj * 8 + rj * 2;
    float* outp = g_kctx + (size_t)(b * 49 + l) * DIMC;
#pragma unroll
    for (int k = 0; k < 32; k++) {
        int c = wid * 32 + k;
        float2 v = *(const float2*)(base + (size_t)c * 3136);
        float s = v.x + v.y;
#pragma unroll
        for (int o = 16; o >= 1; o >>= 1) s += __shfl_xor_sync(0xffffffffu, s, o);
        if (lane == 0) outp[c] = s * (1.f / 64.f);
    }
}

// ---------------- fused stats + fold Wproj -> kfp[bg][m][c] ----------------
__global__ __launch_bounds__(256) void kfp_kernel(const float* __restrict__ Wproj,
                                                  const float* __restrict__ gk,
                                                  const float* __restrict__ bk) {
    __shared__ float smu[49], srs[49];
    __shared__ float sn[49 * 64];     // normalized head slice
    __shared__ float swp[74 * 49];    // Wproj
    int bg = blockIdx.x;
    int b = bg >> 2, gg = bg & 3;
    int tid = threadIdx.x;
    int wid = tid >> 5, lane = tid & 31;

    for (int row = wid; row < 49; row += 8) {
        const float* rp = g_kraw + (size_t)(b * 49 + row) * DIMC;
        float s = 0.f, s2 = 0.f;
#pragma unroll
        for (int i = 0; i < 8; i++) { float t = rp[lane + 32 * i]; s += t; s2 += t * t; }
#pragma unroll
        for (int o = 16; o >= 1; o >>= 1) {
            s  += __shfl_xor_sync(0xffffffffu, s,  o);
            s2 += __shfl_xor_sync(0xffffffffu, s2, o);
        }
        if (lane == 0) {
            float mu = s * (1.f / DIMC);
            float var = s2 * (1.f / DIMC) - mu * mu;
            smu[row] = mu;
            srs[row] = rsqrtf(var + 1e-6f);
        }
    }
    for (int idx = tid; idx < 74 * 49; idx += 256) swp[idx] = Wproj[idx];
    __syncthreads();
    for (int idx = tid; idx < 49 * 64; idx += 256) {
        int l = idx >> 6, c = idx & 63;
        sn[idx] = (g_kraw[(size_t)(b * 49 + l) * DIMC + gg * HD + c] - smu[l]) * srs[l];
    }
    __syncthreads();

    int c = tid & 63, mb = tid >> 6;
    float gkv = gk[gg * HD + c], bkv = bk[gg * HD + c];
    float* outp = g_kfp + (size_t)bg * 80 * 64;
#pragma unroll
    for (int mg = 0; mg < 5; mg++) {
        int m0 = mg * 16 + mb * 4;
        float acc[4] = {0.f, 0.f, 0.f, 0.f};
        float sw[4]  = {0.f, 0.f, 0.f, 0.f};
#pragma unroll 7
        for (int l = 0; l < 49; l++) {
            float v = sn[l * 64 + c];
#pragma unroll
            for (int mm = 0; mm < 4; mm++) {
                int m = m0 + mm;
                float w = (m < 74) ? swp[m * 49 + l] : 0.f;
                acc[mm] += v * w;
                sw[mm]  += w;
            }
        }
#pragma unroll
        for (int mm = 0; mm < 4; mm++) {
            int m = m0 + mm;
            outp[m * 64 + c] = (m < 74) ? acc[mm] * gkv + sw[mm] * bkv : 0.f;
        }
    }
}

// ---------------- wgt mma GEMM [128 x 80 x 64] + RPB + softmax ----------------
__global__ __launch_bounds__(256)
void wgt_mma_kernel(const float* __restrict__ rpb1, const float* __restrict__ rpb2) {
    extern __shared__ char smc[];
    uint32_t* As = (uint32_t*)smc;                 // [128][68]
    uint32_t* Bs = As + 128 * 68;                  // [80][68]
    float*    Wg = (float*)smc;                    // [128][85]
    __shared__ float srpb[169];

    int tid = threadIdx.x;
    int wid = tid >> 5, lane = tid & 31;
    int q = lane >> 2, tq = lane & 3;
    int wm = wid >> 1, wn = wid & 1;
    int m0 = blockIdx.x * 128;
    int gy = blockIdx.y;
    int b  = gy >> 2, g = gy & 3;

    if (g < 2) { if (tid < 81) srpb[tid] = rpb1[g*81 + tid]; }
    else       { if (tid < 169) srpb[tid] = rpb2[(g-2)*169 + tid]; }

    const float* Abase = g_qt + ((size_t)(b * NPOS + m0)) * DIMC + g * HD;
#pragma unroll
    for (int it = 0; it < 8; it++) {
        int slot = tid + it * 256;
        int row = slot >> 4, c4 = slot & 15;
        float4 v = *(const float4*)(Abase + (size_t)row * DIMC + c4 * 4);
        uint4 u = make_uint4(f2tf32(v.x), f2tf32(v.y), f2tf32(v.z), f2tf32(v.w));
        *(uint4*)(As + row * 68 + c4 * 4) = u;
    }
    const float* Bbase = g_kfp + (size_t)gy * 80 * 64;
#pragma unroll
    for (int it = 0; it < 5; it++) {
        int slot = tid + it * 256;
        int mrow = slot >> 4, c4 = slot & 15;
        float4 v = *(const float4*)(Bbase + (size_t)mrow * 64 + c4 * 4);
        uint4 u = make_uint4(f2tf32(v.x), f2tf32(v.y), f2tf32(v.z), f2tf32(v.w));
        *(uint4*)(Bs + mrow * 68 + c4 * 4) = u;
    }
    __syncthreads();

    float c[2][5][4];
#pragma unroll
    for (int mt = 0; mt < 2; mt++)
#pragma unroll
        for (int nt = 0; nt < 5; nt++)
#pragma unroll
            for (int i = 0; i < 4; i++) c[mt][nt][i] = 0.f;

#pragma unroll
    for (int ks = 0; ks < 8; ks++) {
        int k0 = ks * 8;
        uint32_t a[2][4];
#pragma unroll
        for (int mt = 0; mt < 2; mt++) {
            int r = wm * 32 + mt * 16 + q;
            a[mt][0] = As[r * 68 + k0 + tq];
            a[mt][1] = As[(r + 8) * 68 + k0 + tq];
            a[mt][2] = As[r * 68 + k0 + tq + 4];
            a[mt][3] = As[(r + 8) * 68 + k0 + tq + 4];
        }
        uint32_t bfr[5][2];
#pragma unroll
        for (int nt = 0; nt < 5; nt++) {
            int col = wn * 40 + nt * 8 + q;
            bfr[nt][0] = Bs[col * 68 + k0 + tq];
            bfr[nt][1] = Bs[col * 68 + k0 + tq + 4];
        }
#pragma unroll
        for (int mt = 0; mt < 2; mt++)
#pragma unroll
            for (int nt = 0; nt < 5; nt++) {
                asm volatile(
                    "mma.sync.aligned.m16n8k8.row.col.f32.tf32.tf32.f32 "
                    "{%0,%1,%2,%3}, {%4,%5,%6,%7}, {%8,%9}, {%0,%1,%2,%3};"
                    : "+f"(c[mt][nt][0]), "+f"(c[mt][nt][1]),
                      "+f"(c[mt][nt][2]), "+f"(c[mt][nt][3])
                    : "r"(a[mt][0]), "r"(a[mt][1]), "r"(a[mt][2]), "r"(a[mt][3]),
                      "r"(bfr[nt][0]), "r"(bfr[nt][1]));
            }
    }
    __syncthreads();

#pragma unroll
    for (int mt = 0; mt < 2; mt++) {
        int r = wm * 32 + mt * 16 + q;
#pragma unroll
        for (int nt = 0; nt < 5; nt++) {
            int col = wn * 40 + nt * 8 + 2 * tq;
            Wg[r * 85 + col]       = c[mt][nt][0];
            Wg[r * 85 + col + 1]   = c[mt][nt][1];
            Wg[(r+8) * 85 + col]   = c[mt][nt][2];
            Wg[(r+8) * 85 + col+1] = c[mt][nt][3];
        }
    }
    __syncthreads();

    if (tid < 128) {
        int n = m0 + tid;
        int i = n >> 6, j = n & 63;
        float* wrow = Wg + tid * 85;
        float* arow = g_attn + ((size_t)(gy * NPOS + n)) * 52;
        if (g < 2) {
            int si = min(max(i-2,0),HH-5), sj = min(max(j-2,0),WW-5);
            int bi = 4 - (i - si), bj = 4 - (j - sj);
            float mx = -1e30f;
#pragma unroll
            for (int m = 0; m < 25; m++) {
                int p = m / 5, qq = m - p*5;
                float v = wrow[m] + srpb[(bi+p)*9 + bj + qq];
                wrow[m] = v;
                mx = fmaxf(mx, v);
            }
            float sum = 0.f;
#pragma unroll
            for (int m = 0; m < 25; m++) {
                float e = __expf(wrow[m] - mx);
                wrow[m] = e; sum += e;
            }
            float inv = 1.f / sum;
#pragma unroll
            for (int m = 0; m < 25; m++) arow[m] = wrow[m] * inv;
        } else {
            int si = min(max(i-3,0),HH-7), sj = min(max(j-3,0),WW-7);
            int bi = 6 - (i - si), bj = 6 - (j - sj);
            float mx = -1e30f;
#pragma unroll
            for (int t = 0; t < 49; t++) {
                int p = t / 7, qq = t - p*7;
                float v = wrow[25 + t] + srpb[(bi+p)*13 + bj + qq];
                wrow[25 + t] = v;
                mx = fmaxf(mx, v);
            }
            float sum = 0.f;
#pragma unroll
            for (int t = 0; t < 49; t++) {
                float e = __expf(wrow[25 + t] - mx);
                wrow[25 + t] = e; sum += e;
            }
            float inv = 1.f / sum;
#pragma unroll
            for (int t = 0; t < 49; t++) arow[t] = wrow[25 + t] * inv;
        }
    }
}

// ---------------- neighborhood AV (pixel-paired) ----------------
template<int KK>
__device__ __forceinline__ void av_body(const float* __restrict__ x, int g, float* vs) {
    const int HALO = 8 + KK - 1;
    int ti0 = (blockIdx.x >> 3) * 8, tj0 = (blockIdx.x & 7) * 8;
    int b = blockIdx.z;
    int hbi = min(max(ti0 - KK/2, 0), HH - HALO);
    int hbj = min(max(tj0 - KK/2, 0), WW - HALO);
    const float* xb = x + (size_t)(b*DIMC + g*HD)*NPOS;
    for (int idx = threadIdx.x; idx < HALO*HALO*HD; idx += 256) {
        int c  = idx / (HALO*HALO);
        int rr = idx - c*HALO*HALO;
        int ri = rr / HALO, rj = rr - ri*HALO;
        vs[rr*68 + c] = xb[(size_t)c*NPOS + (hbi+ri)*WW + hbj + rj];
    }
    __syncthreads();
    int t = threadIdx.x;
    int pairIdx = t >> 3, cg = t & 7;            // 32 pairs x 8 channel-groups
    int i  = ti0 + (pairIdx >> 2);
    int j0 = tj0 + (pairIdx & 3) * 2;
    int si  = min(max(i  - KK/2, 0), HH-KK) - hbi;
    int sj0 = min(max(j0     - KK/2, 0), WW-KK) - hbj;
    int sj1 = min(max(j0 + 1 - KK/2, 0), WW-KK) - hbj;
    int off1 = sj1 - sj0;                        // 0 or 1; off0 == 0 always
    int n0 = i*WW + j0;
    const float* ar0 = g_attn + ((size_t)((b*NHEAD+g)*NPOS + n0))*52;
    const float* ar1 = ar0 + 52;
    float4 p0a = make_float4(0,0,0,0), p0b = p0a, p1a = p0a, p1b = p0a;
    int qend = KK + off1;
#pragma unroll
    for (int p = 0; p < KK; p++) {
        const float* aw0 = ar0 + p*KK;
        const float* aw1 = ar1 + p*KK - off1;
        const float* vrow = &vs[((si+p)*HALO + sj0)*68 + cg*8];
        for (int q = 0; q < qend; q++) {
            const float4* vp = reinterpret_cast<const float4*>(vrow + q*68);
            float4 v0 = vp[0], v1 = vp[1];
            float w0 = (q < KK) ? __ldg(aw0 + q) : 0.f;
            float w1 = (q >= off1) ? __ldg(aw1 + q) : 0.f;
            p0a.x += w0*v0.x; p0a.y += w0*v0.y; p0a.z += w0*v0.z; p0a.w += w0*v0.w;
            p0b.x += w0*v1.x; p0b.y += w0*v1.y; p0b.z += w0*v1.z; p0b.w += w0*v1.w;
            p1a.x += w1*v0.x; p1a.y += w1*v0.y; p1a.z += w1*v0.z; p1a.w += w1*v0.w;
            p1b.x += w1*v1.x; p1b.y += w1*v1.y; p1b.z += w1*v1.z; p1b.w += w1*v1.w;
        }
    }
    float* op0 = g_mid + ((size_t)(b*NPOS + n0))*DIMC + g*HD + cg*8;
    float* op1 = op0 + DIMC;
    ((float4*)op0)[0] = p0a; ((float4*)op0)[1] = p0b;
    ((float4*)op1)[0] = p1a; ((float4*)op1)[1] = p1b;
}

__global__ __launch_bounds__(256) void av_all_kernel(const float* __restrict__ x) {
    extern __shared__ float vs[];
    int g = blockIdx.y;
    if (g < 2) av_body<5>(x, g, vs);
    else       av_body<7>(x, g, vs);
}

extern "C" void kernel_launch(void* const* d_in, const int* in_sizes, int n_in,
                              void* d_out, int out_size) {
    const float* x     = (const float*)d_in[0];
    const float* ctx   = (const float*)d_in[1];
    const float* Wq    = (const float*)d_in[2];
    const float* gq    = (const float*)d_in[3];
    const float* bq    = (const float*)d_in[4];
    const float* Wk    = (const float*)d_in[5];
    const float* gk    = (const float*)d_in[6];
    const float* bk    = (const float*)d_in[7];
    const float* Wproj = (const float*)d_in[8];
    const float* rpb1  = (const float*)d_in[9];
    const float* rpb2  = (const float*)d_in[10];
    const float* Wdy   = (const float*)d_in[11];
    const float* bn_g  = (const float*)d_in[12];
    const float* bn_b  = (const float*)d_in[13];
    float* out = (float*)d_out;

    const int GSMEM   = 2 * 128 * 36 * 4;                 // 36864
    const int G1SMEM  = (32 * ASTR + 256 * 36) * 4;       // 54272
    const int WGSMEM  = (128 * 68 + 80 * 68) * 4;         // 56576
    const int AVSMEM  = 14 * 14 * 68 * 4;                 // 53312
    cudaFuncSetAttribute(av_all_kernel, cudaFuncAttributeMaxDynamicSharedMemorySize, AVSMEM);
    cudaFuncSetAttribute(gemm1_ln_kernel, cudaFuncAttributeMaxDynamicSharedMemorySize, G1SMEM);
    cudaFuncSetAttribute(wgt_mma_kernel, cudaFuncAttributeMaxDynamicSharedMemorySize, WGSMEM);
    cudaFuncSetAttribute(mma_gemm_kernel<0>, cudaFuncAttributeMaxDynamicSharedMemorySize, GSMEM);
    cudaFuncSetAttribute(mma_gemm_kernel<1>, cudaFuncAttributeMaxDynamicSharedMemorySize, GSMEM);

    static float *p_kctx = nullptr, *p_kraw = nullptr, *p_mid = nullptr;
    if (!p_kctx) {
        cudaGetSymbolAddress((void**)&p_kctx, g_kctx);
        cudaGetSymbolAddress((void**)&p_kraw, g_kraw);
        cudaGetSymbolAddress((void**)&p_mid,  g_mid);
    }

    pool_kernel<<<dim3(49, NB), 256>>>(ctx);
    mma_gemm_kernel<0><<<dim3(2, 2, 1), 256, GSMEM>>>(p_kctx, Wk, p_kraw, nullptr, nullptr, NB*49, 0);
    kfp_kernel<<<NB*NHEAD, 256>>>(Wproj, gk, bk);
    gemm1_ln_kernel<<<dim3(32, 1, NB), 512, G1SMEM>>>(x, Wq, gq, bq);
    wgt_mma_kernel<<<dim3(32, 16), 256, WGSMEM>>>(rpb1, rpb2);
    av_all_kernel<<<dim3(64, 4, NB), 256, AVSMEM>>>(x);
    mma_gemm_kernel<1><<<dim3(32, 2, NB), 256, GSMEM>>>(p_mid, Wdy, out, bn_g, bn_b, NPOS, NPOS*DIMC);
}

// round 11
// speedup vs baseline: 1.8854x; 1.0651x over previous
#include <cuda_runtime.h>
#include <cstdint>
#include <math.h>

#define NB 4
#define DIMC 256
#define HH 64
#define WW 64
#define NPOS (HH*WW)
#define NHEAD 4
#define HD 64

// ---------------- scratch ----------------
__device__ float g_qt[NB*NPOS*DIMC];         // LN(q)*scale [b][n][o]
__device__ float g_kctx[NB*49*DIMC];         // pooled ctx [row=(b*49+l)][c]
__device__ float g_kraw[256*DIMC];           // Wk@kctx raw (196 rows used)
__device__ float g_kfp[NB*NHEAD*80*64];      // folded proj [bg][m<74 pad80][c]
__device__ float g_attn[NB*NHEAD*NPOS*52];   // softmaxed attn
__device__ float g_mid[NB*NPOS*DIMC];        // AV out [b][n][c]

__device__ __forceinline__ void cvt_tf32(uint32_t& r) {
    asm("cvt.rna.tf32.f32 %0, %0;" : "+r"(r));
}
__device__ __forceinline__ void cp16(uint32_t saddr, const void* gaddr) {
    asm volatile("cp.async.ca.shared.global [%0], [%1], 16;" :: "r"(saddr), "l"(gaddr));
}
#define CP_COMMIT() asm volatile("cp.async.commit_group;" ::: "memory")
#define CP_WAIT1()  asm volatile("cp.async.wait_group 1;" ::: "memory")
#define CP_WAIT0()  asm volatile("cp.async.wait_group 0;" ::: "memory")

// ================= gemm1 + fused LN (cp.async double-buffered) =================
#define ASTR 136
#define G1WORDS (32*ASTR + 256*36)     // words per buffer
__global__ __launch_bounds__(512, 1)
void gemm1_ln_kernel(const float* __restrict__ x, const float* __restrict__ Wq,
                     const float* __restrict__ gq, const float* __restrict__ bq) {
    extern __shared__ uint32_t sm[];                 // 2 x (As2[32*ASTR] ++ Bs[256*36])
    __shared__ float red_s[128][9];
    __shared__ float red_s2[128][9];
    __shared__ float sg[256], sb[256];

    int tid  = threadIdx.x;
    int wid  = tid >> 5, lane = tid & 31;
    int q    = lane >> 2, tq = lane & 3;
    int wm   = wid >> 3, wn = wid & 7;               // 2 x 8
    int z    = blockIdx.z;
    int m0   = blockIdx.x * 128;
    const float* xb = x + (size_t)z * DIMC * NPOS;
    uint32_t sbase = (uint32_t)__cvta_generic_to_shared(sm);

    if (tid < 256) { sg[tid] = gq[tid]; sb[tid] = bq[tid]; }

    float c[4][4][4];
#pragma unroll
    for (int mt = 0; mt < 4; mt++)
#pragma unroll
        for (int nt = 0; nt < 4; nt++)
#pragma unroll
            for (int i = 0; i < 4; i++) c[mt][nt][i] = 0.f;

    // issue one chunk's cp.asyncs into buffer s
    auto issue = [&](int ck, int s) {
        uint32_t abase = sbase + (uint32_t)(s * G1WORDS) * 4u;
        uint32_t bbase = abase + 32u * ASTR * 4u;
        // A: 1024 segs (32 c-rows x 32 n-segs)
#pragma unroll
        for (int it = 0; it < 2; it++) {
            int slot = tid + it * 512;
            int cc = slot >> 5, n4 = slot & 31;
            cp16(abase + (uint32_t)(cc * ASTR + n4 * 4) * 4u,
                 xb + (size_t)(ck * 32 + cc) * NPOS + m0 + n4 * 4);
        }
        // B: 2048 segs (256 rows x 8 segs)
#pragma unroll
        for (int it = 0; it < 4; it++) {
            int slot = tid + it * 512;
            int row = slot >> 3, c4 = slot & 7;
            cp16(bbase + (uint32_t)(row * 36 + c4 * 4) * 4u,
                 Wq + (size_t)row * DIMC + ck * 32 + c4 * 4);
        }
        CP_COMMIT();
    };

    issue(0, 0);
    for (int ck = 0; ck < 8; ck++) {
        int s = ck & 1;
        if (ck < 7) { issue(ck + 1, s ^ 1); CP_WAIT1(); }
        else        { CP_WAIT0(); }
        __syncthreads();
        const uint32_t* As2 = sm + s * G1WORDS;
        const uint32_t* Bs  = As2 + 32 * ASTR;
#pragma unroll
        for (int ks = 0; ks < 4; ks++) {
            int k0 = ks * 8;
            uint32_t a[4][4];
#pragma unroll
            for (int mt = 0; mt < 4; mt++) {
                int r = wm * 64 + mt * 16 + q;
                a[mt][0] = As2[(k0 + tq) * ASTR + r];
                a[mt][1] = As2[(k0 + tq) * ASTR + r + 8];
                a[mt][2] = As2[(k0 + tq + 4) * ASTR + r];
                a[mt][3] = As2[(k0 + tq + 4) * ASTR + r + 8];
                cvt_tf32(a[mt][0]); cvt_tf32(a[mt][1]); cvt_tf32(a[mt][2]); cvt_tf32(a[mt][3]);
            }
            uint32_t b[4][2];
#pragma unroll
            for (int nt = 0; nt < 4; nt++) {
                int o = wn * 32 + nt * 8 + q;
                b[nt][0] = Bs[o * 36 + k0 + tq];
                b[nt][1] = Bs[o * 36 + k0 + tq + 4];
                cvt_tf32(b[nt][0]); cvt_tf32(b[nt][1]);
            }
#pragma unroll
            for (int mt = 0; mt < 4; mt++)
#pragma unroll
                for (int nt = 0; nt < 4; nt++) {
                    asm volatile(
                        "mma.sync.aligned.m16n8k8.row.col.f32.tf32.tf32.f32 "
                        "{%0,%1,%2,%3}, {%4,%5,%6,%7}, {%8,%9}, {%0,%1,%2,%3};"
                        : "+f"(c[mt][nt][0]), "+f"(c[mt][nt][1]),
                          "+f"(c[mt][nt][2]), "+f"(c[mt][nt][3])
                        : "r"(a[mt][0]), "r"(a[mt][1]), "r"(a[mt][2]), "r"(a[mt][3]),
                          "r"(b[nt][0]), "r"(b[nt][1]));
                }
        }
        __syncthreads();
    }

    // ---- fused LN epilogue ----
#pragma unroll
    for (int mt = 0; mt < 4; mt++) {
#pragma unroll
        for (int h = 0; h < 2; h++) {
            float s = 0.f, s2 = 0.f;
#pragma unroll
            for (int nt = 0; nt < 4; nt++) {
                float v0 = c[mt][nt][2*h], v1 = c[mt][nt][2*h+1];
                s += v0 + v1; s2 += v0*v0 + v1*v1;
            }
            s  += __shfl_xor_sync(0xffffffffu, s, 1);
            s2 += __shfl_xor_sync(0xffffffffu, s2, 1);
            s  += __shfl_xor_sync(0xffffffffu, s, 2);
            s2 += __shfl_xor_sync(0xffffffffu, s2, 2);
            if (tq == 0) {
                int rl = wm * 64 + mt * 16 + q + h * 8;
                red_s[rl][wn] = s;
                red_s2[rl][wn] = s2;
            }
        }
    }
    __syncthreads();
    float* outb = g_qt + (size_t)z * NPOS * DIMC;
#pragma unroll
    for (int mt = 0; mt < 4; mt++) {
#pragma unroll
        for (int h = 0; h < 2; h++) {
            int rl = wm * 64 + mt * 16 + q + h * 8;
            float S = 0.f, S2 = 0.f;
#pragma unroll
            for (int w = 0; w < 8; w++) { S += red_s[rl][w]; S2 += red_s2[rl][w]; }
            float mu = S * (1.f/256.f);
            float var = S2 * (1.f/256.f) - mu * mu;
            float rs = rsqrtf(var + 1e-6f);
            float* rowp = outb + (size_t)(m0 + rl) * DIMC;
#pragma unroll
            for (int nt = 0; nt < 4; nt++) {
                int o = wn * 32 + nt * 8 + 2 * tq;
                float2 v;
                v.x = ((c[mt][nt][2*h]   - mu) * rs * sg[o]   + sb[o])   * 0.125f;
                v.y = ((c[mt][nt][2*h+1] - mu) * rs * sg[o+1] + sb[o+1]) * 0.125f;
                *(float2*)(rowp + o) = v;
            }
        }
    }
}

// ================= generic mma.sync tf32 GEMM (cp.async double-buffered) =================
#define GWORDS (2 * 128 * 36)          // words per buffer (As 128*36 ++ Bs 128*36)
template<int EPI>
__global__ __launch_bounds__(256, 2)
void mma_gemm_kernel(const float* __restrict__ A, const float* __restrict__ B,
                     float* __restrict__ Out, const float* __restrict__ p1,
                     const float* __restrict__ p2, int mvalid, int batchStride) {
    extern __shared__ uint32_t sm[];   // 2 buffers
    __shared__ float sp1[256], sp2[256];

    int tid = threadIdx.x;
    int wid = tid >> 5;
    int lane = tid & 31;
    int q = lane >> 2, tq = lane & 3;
    int wm = wid >> 2, wn = wid & 3;
    int z = blockIdx.z;
    int m0 = blockIdx.x * 128;
    int n0 = blockIdx.y * 128;
    const float* Ab = A + (size_t)z * batchStride;
    uint32_t sbase = (uint32_t)__cvta_generic_to_shared(sm);

    if (EPI == 1) { sp1[tid] = p1[tid] * rsqrtf(1.f + 1e-5f); sp2[tid] = p2[tid]; }

    float c[4][4][4];
#pragma unroll
    for (int mt = 0; mt < 4; mt++)
#pragma unroll
        for (int nt = 0; nt < 4; nt++)
#pragma unroll
            for (int i = 0; i < 4; i++) c[mt][nt][i] = 0.f;

    auto issue = [&](int ck, int s) {
        uint32_t abase = sbase + (uint32_t)(s * GWORDS) * 4u;
        uint32_t bbase = abase + 128u * 36u * 4u;
#pragma unroll
        for (int t = 0; t < 4; t++) {
            int idx = tid + t * 256;
            int row = idx >> 3, c4 = idx & 7;
            int ga = min(m0 + row, mvalid - 1);
            cp16(abase + (uint32_t)(row * 36 + c4 * 4) * 4u,
                 Ab + (size_t)ga * DIMC + ck * 32 + c4 * 4);
            cp16(bbase + (uint32_t)(row * 36 + c4 * 4) * 4u,
                 B + (size_t)(n0 + row) * DIMC + ck * 32 + c4 * 4);
        }
        CP_COMMIT();
    };

    issue(0, 0);
    for (int ck = 0; ck < 8; ck++) {
        int s = ck & 1;
        if (ck < 7) { issue(ck + 1, s ^ 1); CP_WAIT1(); }
        else        { CP_WAIT0(); }
        __syncthreads();
        const uint32_t* As = sm + s * GWORDS;
        const uint32_t* Bs = As + 128 * 36;
#pragma unroll
        for (int ks = 0; ks < 4; ks++) {
            int k0 = ks * 8;
            uint32_t a[4][4];
#pragma unroll
            for (int mt = 0; mt < 4; mt++) {
                int r = wm * 64 + mt * 16 + q;
                a[mt][0] = As[r * 36 + k0 + tq];
                a[mt][1] = As[(r + 8) * 36 + k0 + tq];
                a[mt][2] = As[r * 36 + k0 + tq + 4];
                a[mt][3] = As[(r + 8) * 36 + k0 + tq + 4];
                cvt_tf32(a[mt][0]); cvt_tf32(a[mt][1]); cvt_tf32(a[mt][2]); cvt_tf32(a[mt][3]);
            }
            uint32_t b[4][2];
#pragma unroll
            for (int nt = 0; nt < 4; nt++) {
                int nn = wn * 32 + nt * 8 + q;
                b[nt][0] = Bs[nn * 36 + k0 + tq];
                b[nt][1] = Bs[nn * 36 + k0 + tq + 4];
                cvt_tf32(b[nt][0]); cvt_tf32(b[nt][1]);
            }
#pragma unroll
            for (int mt = 0; mt < 4; mt++)
#pragma unroll
                for (int nt = 0; nt < 4; nt++) {
                    asm volatile(
                        "mma.sync.aligned.m16n8k8.row.col.f32.tf32.tf32.f32 "
                        "{%0,%1,%2,%3}, {%4,%5,%6,%7}, {%8,%9}, {%0,%1,%2,%3};"
                        : "+f"(c[mt][nt][0]), "+f"(c[mt][nt][1]),
                          "+f"(c[mt][nt][2]), "+f"(c[mt][nt][3])
                        : "r"(a[mt][0]), "r"(a[mt][1]), "r"(a[mt][2]), "r"(a[mt][3]),
                          "r"(b[nt][0]), "r"(b[nt][1]));
                }
        }
        __syncthreads();
    }

#pragma unroll
    for (int mt = 0; mt < 4; mt++) {
        int r0 = m0 + wm * 64 + mt * 16 + q;
#pragma unroll
        for (int nt = 0; nt < 4; nt++) {
            int o0 = n0 + wn * 32 + nt * 8 + 2 * tq;
            if (EPI == 0) {
                if (r0 < mvalid) {
                    float2 v = make_float2(c[mt][nt][0], c[mt][nt][1]);
                    *(float2*)(Out + (size_t)(z * NPOS + r0) * DIMC + o0) = v;
                }
                if (r0 + 8 < mvalid) {
                    float2 v = make_float2(c[mt][nt][2], c[mt][nt][3]);
                    *(float2*)(Out + (size_t)(z * NPOS + r0 + 8) * DIMC + o0) = v;
                }
            } else {
                float s0 = sp1[o0],     h0 = sp2[o0];
                float s1 = sp1[o0 + 1], h1 = sp2[o0 + 1];
                float* base0 = Out + ((size_t)(z * DIMC + o0)) * NPOS;
                float* base1 = Out + ((size_t)(z * DIMC + o0 + 1)) * NPOS;
                base0[r0]     = c[mt][nt][0] * s0 + h0;
                base1[r0]     = c[mt][nt][1] * s1 + h1;
                base0[r0 + 8] = c[mt][nt][2] * s0 + h0;
                base1[r0 + 8] = c[mt][nt][3] * s1 + h1;
            }
        }
    }
}

// ---------------- ctx 8x8 avg pool (warp-per-channel) ----------------
__global__ __launch_bounds__(256) void pool_kernel(const float* __restrict__ ctx) {
    int l = blockIdx.x, b = blockIdx.y;
    int li = l / 7, lj = l % 7;
    int wid = threadIdx.x >> 5, lane = threadIdx.x & 31;
    int ri = lane >> 2, rj = lane & 3;
    const float* base = ctx + (size_t)b * DIMC * 3136 + (li * 8 + ri) * 56 + lj * 8 + rj * 2;
    float* outp = g_kctx + (size_t)(b * 49 + l) * DIMC;
#pragma unroll
    for (int k = 0; k < 32; k++) {
        int c = wid * 32 + k;
        float2 v = *(const float2*)(base + (size_t)c * 3136);
        float s = v.x + v.y;
#pragma unroll
        for (int o = 16; o >= 1; o >>= 1) s += __shfl_xor_sync(0xffffffffu, s, o);
        if (lane == 0) outp[c] = s * (1.f / 64.f);
    }
}

// ---------------- fused stats + fold Wproj -> kfp[bg][m][c] ----------------
__global__ __launch_bounds__(256) void kfp_kernel(const float* __restrict__ Wproj,
                                                  const float* __restrict__ gk,
                                                  const float* __restrict__ bk) {
    __shared__ float smu[49], srs[49];
    __shared__ float sn[49 * 64];
    __shared__ float swp[74 * 49];
    int bg = blockIdx.x;
    int b = bg >> 2, gg = bg & 3;
    int tid = threadIdx.x;
    int wid = tid >> 5, lane = tid & 31;

    for (int row = wid; row < 49; row += 8) {
        const float* rp = g_kraw + (size_t)(b * 49 + row) * DIMC;
        float s = 0.f, s2 = 0.f;
#pragma unroll
        for (int i = 0; i < 8; i++) { float t = rp[lane + 32 * i]; s += t; s2 += t * t; }
#pragma unroll
        for (int o = 16; o >= 1; o >>= 1) {
            s  += __shfl_xor_sync(0xffffffffu, s,  o);
            s2 += __shfl_xor_sync(0xffffffffu, s2, o);
        }
        if (lane == 0) {
            float mu = s * (1.f / DIMC);
            float var = s2 * (1.f / DIMC) - mu * mu;
            smu[row] = mu;
            srs[row] = rsqrtf(var + 1e-6f);
        }
    }
    for (int idx = tid; idx < 74 * 49; idx += 256) swp[idx] = Wproj[idx];
    __syncthreads();
    for (int idx = tid; idx < 49 * 64; idx += 256) {
        int l = idx >> 6, c = idx & 63;
        sn[idx] = (g_kraw[(size_t)(b * 49 + l) * DIMC + gg * HD + c] - smu[l]) * srs[l];
    }
    __syncthreads();

    int c = tid & 63, mb = tid >> 6;
    float gkv = gk[gg * HD + c], bkv = bk[gg * HD + c];
    float* outp = g_kfp + (size_t)bg * 80 * 64;
#pragma unroll
    for (int mg = 0; mg < 5; mg++) {
        int m0 = mg * 16 + mb * 4;
        float acc[4] = {0.f, 0.f, 0.f, 0.f};
        float sw[4]  = {0.f, 0.f, 0.f, 0.f};
#pragma unroll 7
        for (int l = 0; l < 49; l++) {
            float v = sn[l * 64 + c];
#pragma unroll
            for (int mm = 0; mm < 4; mm++) {
                int m = m0 + mm;
                float w = (m < 74) ? swp[m * 49 + l] : 0.f;
                acc[mm] += v * w;
                sw[mm]  += w;
            }
        }
#pragma unroll
        for (int mm = 0; mm < 4; mm++) {
            int m = m0 + mm;
            outp[m * 64 + c] = (m < 74) ? acc[mm] * gkv + sw[mm] * bkv : 0.f;
        }
    }
}

// ---------------- wgt mma GEMM [128 x 80 x 64] + RPB + softmax ----------------
__global__ __launch_bounds__(256)
void wgt_mma_kernel(const float* __restrict__ rpb1, const float* __restrict__ rpb2) {
    extern __shared__ char smc[];
    uint32_t* As = (uint32_t*)smc;                 // [128][68]
    uint32_t* Bs = As + 128 * 68;                  // [80][68]
    float*    Wg = (float*)smc;                    // [128][85]
    __shared__ float srpb[169];

    int tid = threadIdx.x;
    int wid = tid >> 5, lane = tid & 31;
    int q = lane >> 2, tq = lane & 3;
    int wm = wid >> 1, wn = wid & 1;
    int m0 = blockIdx.x * 128;
    int gy = blockIdx.y;
    int b  = gy >> 2, g = gy & 3;

    if (g < 2) { if (tid < 81) srpb[tid] = rpb1[g*81 + tid]; }
    else       { if (tid < 169) srpb[tid] = rpb2[(g-2)*169 + tid]; }

    const float* Abase = g_qt + ((size_t)(b * NPOS + m0)) * DIMC + g * HD;
#pragma unroll
    for (int it = 0; it < 8; it++) {
        int slot = tid + it * 256;
        int row = slot >> 4, c4 = slot & 15;
        float4 v = *(const float4*)(Abase + (size_t)row * DIMC + c4 * 4);
        uint4 u;
        u.x = __float_as_uint(v.x); u.y = __float_as_uint(v.y);
        u.z = __float_as_uint(v.z); u.w = __float_as_uint(v.w);
        cvt_tf32(u.x); cvt_tf32(u.y); cvt_tf32(u.z); cvt_tf32(u.w);
        *(uint4*)(As + row * 68 + c4 * 4) = u;
    }
    const float* Bbase = g_kfp + (size_t)gy * 80 * 64;
#pragma unroll
    for (int it = 0; it < 5; it++) {
        int slot = tid + it * 256;
        int mrow = slot >> 4, c4 = slot & 15;
        float4 v = *(const float4*)(Bbase + (size_t)mrow * 64 + c4 * 4);
        uint4 u;
        u.x = __float_as_uint(v.x); u.y = __float_as_uint(v.y);
        u.z = __float_as_uint(v.z); u.w = __float_as_uint(v.w);
        cvt_tf32(u.x); cvt_tf32(u.y); cvt_tf32(u.z); cvt_tf32(u.w);
        *(uint4*)(Bs + mrow * 68 + c4 * 4) = u;
    }
    __syncthreads();

    float c[2][5][4];
#pragma unroll
    for (int mt = 0; mt < 2; mt++)
#pragma unroll
        for (int nt = 0; nt < 5; nt++)
#pragma unroll
            for (int i = 0; i < 4; i++) c[mt][nt][i] = 0.f;

#pragma unroll
    for (int ks = 0; ks < 8; ks++) {
        int k0 = ks * 8;
        uint32_t a[2][4];
#pragma unroll
        for (int mt = 0; mt < 2; mt++) {
            int r = wm * 32 + mt * 16 + q;
            a[mt][0] = As[r * 68 + k0 + tq];
            a[mt][1] = As[(r + 8) * 68 + k0 + tq];
            a[mt][2] = As[r * 68 + k0 + tq + 4];
            a[mt][3] = As[(r + 8) * 68 + k0 + tq + 4];
        }
        uint32_t bfr[5][2];
#pragma unroll
        for (int nt = 0; nt < 5; nt++) {
            int col = wn * 40 + nt * 8 + q;
            bfr[nt][0] = Bs[col * 68 + k0 + tq];
            bfr[nt][1] = Bs[col * 68 + k0 + tq + 4];
        }
#pragma unroll
        for (int mt = 0; mt < 2; mt++)
#pragma unroll
            for (int nt = 0; nt < 5; nt++) {
                asm volatile(
                    "mma.sync.aligned.m16n8k8.row.col.f32.tf32.tf32.f32 "
                    "{%0,%1,%2,%3}, {%4,%5,%6,%7}, {%8,%9}, {%0,%1,%2,%3};"
                    : "+f"(c[mt][nt][0]), "+f"(c[mt][nt][1]),
                      "+f"(c[mt][nt][2]), "+f"(c[mt][nt][3])
                    : "r"(a[mt][0]), "r"(a[mt][1]), "r"(a[mt][2]), "r"(a[mt][3]),
                      "r"(bfr[nt][0]), "r"(bfr[nt][1]));
            }
    }
    __syncthreads();

#pragma unroll
    for (int mt = 0; mt < 2; mt++) {
        int r = wm * 32 + mt * 16 + q;
#pragma unroll
        for (int nt = 0; nt < 5; nt++) {
            int col = wn * 40 + nt * 8 + 2 * tq;
            Wg[r * 85 + col]       = c[mt][nt][0];
            Wg[r * 85 + col + 1]   = c[mt][nt][1];
            Wg[(r+8) * 85 + col]   = c[mt][nt][2];
            Wg[(r+8) * 85 + col+1] = c[mt][nt][3];
        }
    }
    __syncthreads();

    if (tid < 128) {
        int n = m0 + tid;
        int i = n >> 6, j = n & 63;
        float* wrow = Wg + tid * 85;
        float* arow = g_attn + ((size_t)(gy * NPOS + n)) * 52;
        if (g < 2) {
            int si = min(max(i-2,0),HH-5), sj = min(max(j-2,0),WW-5);
            int bi = 4 - (i - si), bj = 4 - (j - sj);
            float mx = -1e30f;
#pragma unroll
            for (int m = 0; m < 25; m++) {
                int p = m / 5, qq = m - p*5;
                float v = wrow[m] + srpb[(bi+p)*9 + bj + qq];
                wrow[m] = v;
                mx = fmaxf(mx, v);
            }
            float sum = 0.f;
#pragma unroll
            for (int m = 0; m < 25; m++) {
                float e = __expf(wrow[m] - mx);
                wrow[m] = e; sum += e;
            }
            float inv = 1.f / sum;
#pragma unroll
            for (int m = 0; m < 25; m++) arow[m] = wrow[m] * inv;
        } else {
            int si = min(max(i-3,0),HH-7), sj = min(max(j-3,0),WW-7);
            int bi = 6 - (i - si), bj = 6 - (j - sj);
            float mx = -1e30f;
#pragma unroll
            for (int t = 0; t < 49; t++) {
                int p = t / 7, qq = t - p*7;
                float v = wrow[25 + t] + srpb[(bi+p)*13 + bj + qq];
                wrow[25 + t] = v;
                mx = fmaxf(mx, v);
            }
            float sum = 0.f;
#pragma unroll
            for (int t = 0; t < 49; t++) {
                float e = __expf(wrow[25 + t] - mx);
                wrow[25 + t] = e; sum += e;
            }
            float inv = 1.f / sum;
#pragma unroll
            for (int t = 0; t < 49; t++) arow[t] = wrow[25 + t] * inv;
        }
    }
}

// ---------------- neighborhood AV (pixel-paired) ----------------
template<int KK>
__device__ __forceinline__ void av_body(const float* __restrict__ x, int g, float* vs) {
    const int HALO = 8 + KK - 1;
    int ti0 = (blockIdx.x >> 3) * 8, tj0 = (blockIdx.x & 7) * 8;
    int b = blockIdx.z;
    int hbi = min(max(ti0 - KK/2, 0), HH - HALO);
    int hbj = min(max(tj0 - KK/2, 0), WW - HALO);
    const float* xb = x + (size_t)(b*DIMC + g*HD)*NPOS;
    for (int idx = threadIdx.x; idx < HALO*HALO*HD; idx += 256) {
        int c  = idx / (HALO*HALO);
        int rr = idx - c*HALO*HALO;
        int ri = rr / HALO, rj = rr - ri*HALO;
        vs[rr*68 + c] = xb[(size_t)c*NPOS + (hbi+ri)*WW + hbj + rj];
    }
    __syncthreads();
    int t = threadIdx.x;
    int pairIdx = t >> 3, cg = t & 7;
    int i  = ti0 + (pairIdx >> 2);
    int j0 = tj0 + (pairIdx & 3) * 2;
    int si  = min(max(i  - KK/2, 0), HH-KK) - hbi;
    int sj0 = min(max(j0     - KK/2, 0), WW-KK) - hbj;
    int sj1 = min(max(j0 + 1 - KK/2, 0), WW-KK) - hbj;
    int off1 = sj1 - sj0;
    int n0 = i*WW + j0;
    const float* ar0 = g_attn + ((size_t)((b*NHEAD+g)*NPOS + n0))*52;
    const float* ar1 = ar0 + 52;
    float4 p0a = make_float4(0,0,0,0), p0b = p0a, p1a = p0a, p1b = p0a;
    int qend = KK + off1;
#pragma unroll
    for (int p = 0; p < KK; p++) {
        const float* aw0 = ar0 + p*KK;
        const float* aw1 = ar1 + p*KK - off1;
        const float* vrow = &vs[((si+p)*HALO + sj0)*68 + cg*8];
        for (int q = 0; q < qend; q++) {
            const float4* vp = reinterpret_cast<const float4*>(vrow + q*68);
            float4 v0 = vp[0], v1 = vp[1];
            float w0 = (q < KK) ? __ldg(aw0 + q) : 0.f;
            float w1 = (q >= off1) ? __ldg(aw1 + q) : 0.f;
            p0a.x += w0*v0.x; p0a.y += w0*v0.y; p0a.z += w0*v0.z; p0a.w += w0*v0.w;
            p0b.x += w0*v1.x; p0b.y += w0*v1.y; p0b.z += w0*v1.z; p0b.w += w0*v1.w;
            p1a.x += w1*v0.x; p1a.y += w1*v0.y; p1a.z += w1*v0.z; p1a.w += w1*v0.w;
            p1b.x += w1*v1.x; p1b.y += w1*v1.y; p1b.z += w1*v1.z; p1b.w += w1*v1.w;
        }
    }
    float* op0 = g_mid + ((size_t)(b*NPOS + n0))*DIMC + g*HD + cg*8;
    float* op1 = op0 + DIMC;
    ((float4*)op0)[0] = p0a; ((float4*)op0)[1] = p0b;
    ((float4*)op1)[0] = p1a; ((float4*)op1)[1] = p1b;
}

__global__ __launch_bounds__(256) void av_all_kernel(const float* __restrict__ x) {
    extern __shared__ float vs[];
    int g = blockIdx.y;
    if (g < 2) av_body<5>(x, g, vs);
    else       av_body<7>(x, g, vs);
}

extern "C" void kernel_launch(void* const* d_in, const int* in_sizes, int n_in,
                              void* d_out, int out_size) {
    const float* x     = (const float*)d_in[0];
    const float* ctx   = (const float*)d_in[1];
    const float* Wq    = (const float*)d_in[2];
    const float* gq    = (const float*)d_in[3];
    const float* bq    = (const float*)d_in[4];
    const float* Wk    = (const float*)d_in[5];
    const float* gk    = (const float*)d_in[6];
    const float* bk    = (const float*)d_in[7];
    const float* Wproj = (const float*)d_in[8];
    const float* rpb1  = (const float*)d_in[9];
    const float* rpb2  = (const float*)d_in[10];
    const float* Wdy   = (const float*)d_in[11];
    const float* bn_g  = (const float*)d_in[12];
    const float* bn_b  = (const float*)d_in[13];
    float* out = (float*)d_out;

    const int GSMEM   = 2 * GWORDS * 4;                   // 73728
    const int G1SMEM  = 2 * G1WORDS * 4;                  // 108544
    const int WGSMEM  = (128 * 68 + 80 * 68) * 4;         // 56576
    const int AVSMEM  = 14 * 14 * 68 * 4;                 // 53312
    cudaFuncSetAttribute(av_all_kernel, cudaFuncAttributeMaxDynamicSharedMemorySize, AVSMEM);
    cudaFuncSetAttribute(gemm1_ln_kernel, cudaFuncAttributeMaxDynamicSharedMemorySize, G1SMEM);
    cudaFuncSetAttribute(wgt_mma_kernel, cudaFuncAttributeMaxDynamicSharedMemorySize, WGSMEM);
    cudaFuncSetAttribute(mma_gemm_kernel<0>, cudaFuncAttributeMaxDynamicSharedMemorySize, GSMEM);
    cudaFuncSetAttribute(mma_gemm_kernel<1>, cudaFuncAttributeMaxDynamicSharedMemorySize, GSMEM);

    static float *p_kctx = nullptr, *p_kraw = nullptr, *p_mid = nullptr;
    if (!p_kctx) {
        cudaGetSymbolAddress((void**)&p_kctx, g_kctx);
        cudaGetSymbolAddress((void**)&p_kraw, g_kraw);
        cudaGetSymbolAddress((void**)&p_mid,  g_mid);
    }

    pool_kernel<<<dim3(49, NB), 256>>>(ctx);
    mma_gemm_kernel<0><<<dim3(2, 2, 1), 256, GSMEM>>>(p_kctx, Wk, p_kraw, nullptr, nullptr, NB*49, 0);
    kfp_kernel<<<NB*NHEAD, 256>>>(Wproj, gk, bk);
    gemm1_ln_kernel<<<dim3(32, 1, NB), 512, G1SMEM>>>(x, Wq, gq, bq);
    wgt_mma_kernel<<<dim3(32, 16), 256, WGSMEM>>>(rpb1, rpb2);
    av_all_kernel<<<dim3(64, 4, NB), 256, AVSMEM>>>(x);
    mma_gemm_kernel<1><<<dim3(32, 2, NB), 256, GSMEM>>>(p_mid, Wdy, out, bn_g, bn_b, NPOS, NPOS*DIMC);
}